// round 1
// baseline (speedup 1.0000x reference)
#include <cuda_runtime.h>

#define N_NODES 50000
#define N_EDGES 800000
#define F_IN    128
#define HID     256

// ---------------- scratch (device globals; no allocation allowed) ----------------
__device__ int   g_deg[N_NODES];
__device__ int   g_off[N_NODES + 1];
__device__ int   g_cur[N_NODES];
__device__ int   g_csr[N_EDGES];
__device__ float g_agg1[(size_t)N_NODES * F_IN];
__device__ float g_h1  [(size_t)N_NODES * HID];
__device__ float g_agg2[(size_t)N_NODES * HID];

// ---------------- CSR build ----------------
__global__ void count_kernel(const int* __restrict__ dst) {
    int e = blockIdx.x * blockDim.x + threadIdx.x;
    if (e < N_EDGES) atomicAdd(&g_deg[dst[e]], 1);
}

__global__ void scan_kernel() {
    __shared__ int part[1024];
    int tid = threadIdx.x;
    const int chunk = (N_NODES + 1023) / 1024;
    int s = tid * chunk;
    int e = min(s + chunk, N_NODES);
    int sum = 0;
    for (int i = s; i < e; i++) sum += g_deg[i];
    part[tid] = sum;
    __syncthreads();
    #pragma unroll
    for (int o = 1; o < 1024; o <<= 1) {
        int add = (tid >= o) ? part[tid - o] : 0;
        __syncthreads();
        part[tid] += add;
        __syncthreads();
    }
    int run = part[tid] - sum;  // exclusive base
    for (int i = s; i < e; i++) { g_off[i] = run; run += g_deg[i]; }
    if (tid == 1023) g_off[N_NODES] = part[1023];
}

__global__ void fill_kernel(const int* __restrict__ src, const int* __restrict__ dst) {
    int e = blockIdx.x * blockDim.x + threadIdx.x;
    if (e >= N_EDGES) return;
    int d = dst[e];
    int pos = g_off[d] + atomicAdd(&g_cur[d], 1);
    g_csr[pos] = src[e];
}

// ---------------- mean aggregation: one warp per node ----------------
template <int F>
__global__ void agg_kernel(const float* __restrict__ feat, float* __restrict__ out) {
    int node = blockIdx.x * (blockDim.x >> 5) + (threadIdx.x >> 5);
    if (node >= N_NODES) return;
    int lane = threadIdx.x & 31;
    constexpr int V = F / 128;   // float4 chunks per lane
    float4 acc[V];
    #pragma unroll
    for (int v = 0; v < V; v++) acc[v] = make_float4(0.f, 0.f, 0.f, 0.f);
    int s = g_off[node], e = g_off[node + 1];
    for (int i = s; i < e; i++) {
        int src = g_csr[i];
        const float4* row = reinterpret_cast<const float4*>(feat + (size_t)src * F);
        #pragma unroll
        for (int v = 0; v < V; v++) {
            float4 t = row[lane + 32 * v];
            acc[v].x += t.x; acc[v].y += t.y; acc[v].z += t.z; acc[v].w += t.w;
        }
    }
    float inv = (e > s) ? 1.0f / (float)(e - s) : 0.0f;
    float4* orow = reinterpret_cast<float4*>(out + (size_t)node * F);
    #pragma unroll
    for (int v = 0; v < V; v++) {
        acc[v].x *= inv; acc[v].y *= inv; acc[v].z *= inv; acc[v].w *= inv;
        orow[lane + 32 * v] = acc[v];
    }
}

// ---------------- dual-input SGEMM: C = act(A1*B1^T + A2*B2^T + bias) ----------------
// A: [M,K] row-major, B: [N,K] row-major. BM=128, BN=64, BK=16, 256 threads, 8x4 microtile.
template <bool RELU>
__global__ __launch_bounds__(256)
void gemm_dual(const float* __restrict__ A1, const float* __restrict__ B1,
               const float* __restrict__ A2, const float* __restrict__ B2,
               const float* __restrict__ bias, float* __restrict__ C,
               int M, int N, int K) {
    const int BM = 128, BN = 64, BK = 16;
    __shared__ float As[BK][BM];
    __shared__ float Bs[BK][BN];

    int tid = threadIdx.x;
    int m0 = blockIdx.y * BM;
    int n0 = blockIdx.x * BN;
    int tr = tid >> 4;        // 0..15 -> rows tr*8..tr*8+7
    int tc = tid & 15;        // 0..15 -> cols tc*4..tc*4+3

    float acc[8][4];
    #pragma unroll
    for (int i = 0; i < 8; i++)
        #pragma unroll
        for (int j = 0; j < 4; j++) acc[i][j] = 0.f;

    #pragma unroll
    for (int half = 0; half < 2; half++) {
        const float* A = half ? A2 : A1;
        const float* B = half ? B2 : B1;
        for (int kt = 0; kt < K; kt += BK) {
            // load A tile: 128x16 = 512 float4, 2 per thread, stored transposed
            #pragma unroll
            for (int l = 0; l < 2; l++) {
                int idx = tid + l * 256;
                int row = idx >> 2;
                int kc  = (idx & 3) * 4;
                float4 a = make_float4(0.f, 0.f, 0.f, 0.f);
                if (m0 + row < M)
                    a = *reinterpret_cast<const float4*>(A + (size_t)(m0 + row) * K + kt + kc);
                As[kc + 0][row] = a.x;
                As[kc + 1][row] = a.y;
                As[kc + 2][row] = a.z;
                As[kc + 3][row] = a.w;
            }
            // load B tile: 64x16 = 256 float4, 1 per thread
            {
                int row = tid >> 2;
                int kc  = (tid & 3) * 4;
                float4 b = *reinterpret_cast<const float4*>(B + (size_t)(n0 + row) * K + kt + kc);
                Bs[kc + 0][row] = b.x;
                Bs[kc + 1][row] = b.y;
                Bs[kc + 2][row] = b.z;
                Bs[kc + 3][row] = b.w;
            }
            __syncthreads();
            #pragma unroll
            for (int k = 0; k < BK; k++) {
                float4 a0 = *reinterpret_cast<const float4*>(&As[k][tr * 8]);
                float4 a1 = *reinterpret_cast<const float4*>(&As[k][tr * 8 + 4]);
                float4 bv = *reinterpret_cast<const float4*>(&Bs[k][tc * 4]);
                float a[8] = {a0.x, a0.y, a0.z, a0.w, a1.x, a1.y, a1.z, a1.w};
                float b[4] = {bv.x, bv.y, bv.z, bv.w};
                #pragma unroll
                for (int i = 0; i < 8; i++)
                    #pragma unroll
                    for (int j = 0; j < 4; j++)
                        acc[i][j] += a[i] * b[j];
            }
            __syncthreads();
        }
    }

    #pragma unroll
    for (int i = 0; i < 8; i++) {
        int m = m0 + tr * 8 + i;
        if (m >= M) continue;
        #pragma unroll
        for (int j = 0; j < 4; j++) {
            int n = n0 + tc * 4 + j;
            float v = acc[i][j] + bias[n];
            if (RELU) v = fmaxf(v, 0.f);
            C[(size_t)m * N + n] = v;
        }
    }
}

// ---------------- heads: out1 = h@Wh1^T + bh1 (4), out2 = h@Wh2^T + bh2 (3) ----------------
__global__ void heads_kernel(const float* __restrict__ h,
                             const float* __restrict__ Wh1, const float* __restrict__ bh1,
                             const float* __restrict__ Wh2, const float* __restrict__ bh2,
                             float* __restrict__ out1, float* __restrict__ out2) {
    int node = blockIdx.x * (blockDim.x >> 5) + (threadIdx.x >> 5);
    if (node >= N_NODES) return;
    int lane = threadIdx.x & 31;
    const float4* row = reinterpret_cast<const float4*>(h + (size_t)node * HID);
    float4 r0 = row[lane];
    float4 r1 = row[lane + 32];
    float s[7];
    #pragma unroll
    for (int o = 0; o < 7; o++) {
        const float* w = (o < 4) ? (Wh1 + o * HID) : (Wh2 + (o - 4) * HID);
        const float4* wr = reinterpret_cast<const float4*>(w);
        float4 w0 = wr[lane];
        float4 w1 = wr[lane + 32];
        s[o] = r0.x * w0.x + r0.y * w0.y + r0.z * w0.z + r0.w * w0.w
             + r1.x * w1.x + r1.y * w1.y + r1.z * w1.z + r1.w * w1.w;
    }
    #pragma unroll
    for (int o = 0; o < 7; o++)
        #pragma unroll
        for (int d = 16; d > 0; d >>= 1)
            s[o] += __shfl_down_sync(0xffffffffu, s[o], d);
    if (lane == 0) {
        #pragma unroll
        for (int o = 0; o < 4; o++) out1[(size_t)node * 4 + o] = s[o] + bh1[o];
        #pragma unroll
        for (int o = 0; o < 3; o++) out2[(size_t)node * 3 + o] = s[4 + o] + bh2[o];
    }
}

// ---------------- launch ----------------
extern "C" void kernel_launch(void* const* d_in, const int* in_sizes, int n_in,
                              void* d_out, int out_size) {
    const float* x   = (const float*)d_in[0];
    const int*   ei  = (const int*)  d_in[1];
    const float* W1l = (const float*)d_in[2];
    const float* b1l = (const float*)d_in[3];
    const float* W1r = (const float*)d_in[4];
    const float* W2l = (const float*)d_in[5];
    const float* b2l = (const float*)d_in[6];
    const float* W2r = (const float*)d_in[7];
    const float* Wh1 = (const float*)d_in[8];
    const float* bh1 = (const float*)d_in[9];
    const float* Wh2 = (const float*)d_in[10];
    const float* bh2 = (const float*)d_in[11];

    float* out  = (float*)d_out;
    float* out1 = out;                                  // [N,4]
    float* out2 = out + (size_t)N_NODES * 4;            // [N,3]
    float* hout = out + (size_t)N_NODES * 7;            // [N,256]

    const int* src = ei;             // edge_index[0]
    const int* dst = ei + N_EDGES;   // edge_index[1]

    void *p_deg, *p_cur, *p_agg1, *p_h1, *p_agg2;
    cudaGetSymbolAddress(&p_deg,  g_deg);
    cudaGetSymbolAddress(&p_cur,  g_cur);
    cudaGetSymbolAddress(&p_agg1, g_agg1);
    cudaGetSymbolAddress(&p_h1,   g_h1);
    cudaGetSymbolAddress(&p_agg2, g_agg2);

    cudaMemsetAsync(p_deg, 0, N_NODES * sizeof(int));
    cudaMemsetAsync(p_cur, 0, N_NODES * sizeof(int));

    count_kernel<<<(N_EDGES + 255) / 256, 256>>>(dst);
    scan_kernel<<<1, 1024>>>();
    fill_kernel<<<(N_EDGES + 255) / 256, 256>>>(src, dst);

    // layer 1
    agg_kernel<F_IN><<<(N_NODES + 7) / 8, 256>>>(x, (float*)p_agg1);
    dim3 g1(HID / 64, (N_NODES + 127) / 128);
    gemm_dual<true><<<g1, 256>>>((const float*)p_agg1, W1l, x, W1r, b1l,
                                 (float*)p_h1, N_NODES, HID, F_IN);
    // layer 2
    agg_kernel<HID><<<(N_NODES + 7) / 8, 256>>>((const float*)p_h1, (float*)p_agg2);
    gemm_dual<false><<<g1, 256>>>((const float*)p_agg2, W2l, (const float*)p_h1, W2r, b2l,
                                  hout, N_NODES, HID, HID);
    // heads
    heads_kernel<<<(N_NODES + 7) / 8, 256>>>(hout, Wh1, bh1, Wh2, bh2, out1, out2);
}

// round 3
// speedup vs baseline: 1.8466x; 1.8466x over previous
#include <cuda_runtime.h>
#include <cstdint>

#define N_NODES 50000
#define N_EDGES 800000
#define F_IN    128
#define HID     256

// ---------------- scratch (device globals; no allocation allowed) ----------------
__device__ int   g_deg[N_NODES];
__device__ int   g_off[N_NODES + 1];
__device__ int   g_cur[N_NODES];
__device__ int   g_csr[N_EDGES];
__device__ float g_agg1[(size_t)N_NODES * F_IN];
__device__ float g_h1  [(size_t)N_NODES * HID];
__device__ float g_agg2[(size_t)N_NODES * HID];

// ---------------- CSR build ----------------
__global__ void count_kernel(const int* __restrict__ dst) {
    int e = blockIdx.x * blockDim.x + threadIdx.x;
    if (e < N_EDGES) atomicAdd(&g_deg[dst[e]], 1);
}

__global__ void scan_kernel() {
    __shared__ int part[1024];
    int tid = threadIdx.x;
    const int chunk = (N_NODES + 1023) / 1024;
    int s = tid * chunk;
    int e = min(s + chunk, N_NODES);
    int sum = 0;
    for (int i = s; i < e; i++) sum += g_deg[i];
    part[tid] = sum;
    __syncthreads();
    #pragma unroll
    for (int o = 1; o < 1024; o <<= 1) {
        int add = (tid >= o) ? part[tid - o] : 0;
        __syncthreads();
        part[tid] += add;
        __syncthreads();
    }
    int run = part[tid] - sum;  // exclusive base
    for (int i = s; i < e; i++) { g_off[i] = run; run += g_deg[i]; }
    if (tid == 1023) g_off[N_NODES] = part[1023];
}

__global__ void fill_kernel(const int* __restrict__ src, const int* __restrict__ dst) {
    int e = blockIdx.x * blockDim.x + threadIdx.x;
    if (e >= N_EDGES) return;
    int d = dst[e];
    int pos = g_off[d] + atomicAdd(&g_cur[d], 1);
    g_csr[pos] = src[e];
}

// ---------------- mean aggregation: one warp per node ----------------
template <int F>
__global__ void agg_kernel(const float* __restrict__ feat, float* __restrict__ out) {
    int node = blockIdx.x * (blockDim.x >> 5) + (threadIdx.x >> 5);
    if (node >= N_NODES) return;
    int lane = threadIdx.x & 31;
    constexpr int V = F / 128;   // float4 chunks per lane
    float4 acc[V];
    #pragma unroll
    for (int v = 0; v < V; v++) acc[v] = make_float4(0.f, 0.f, 0.f, 0.f);
    int s = g_off[node], e = g_off[node + 1];
    for (int i = s; i < e; i++) {
        int src = g_csr[i];
        const float4* row = reinterpret_cast<const float4*>(feat + (size_t)src * F);
        #pragma unroll
        for (int v = 0; v < V; v++) {
            float4 t = row[lane + 32 * v];
            acc[v].x += t.x; acc[v].y += t.y; acc[v].z += t.z; acc[v].w += t.w;
        }
    }
    float inv = (e > s) ? 1.0f / (float)(e - s) : 0.0f;
    float4* orow = reinterpret_cast<float4*>(out + (size_t)node * F);
    #pragma unroll
    for (int v = 0; v < V; v++) {
        acc[v].x *= inv; acc[v].y *= inv; acc[v].z *= inv; acc[v].w *= inv;
        orow[lane + 32 * v] = acc[v];
    }
}

// ======================= tf32 mma.sync dual GEMM =======================
// C[M, 256] = act( A1[M,K1] * B1[256,K1]^T + A2[M,K2] * B2[256,K2]^T + bias )
// CTA tile 128x128 (grid: M-tiles x 2), BK=16, 8 warps of 64x32.
// mma.sync.m16n8k8 tf32 — compiles at compute_103 (sm_80+ baseline feature).

#define BM 128
#define BN 128
#define BK 16
#define SPAD 20   // smem row stride in 32-bit words (16 data + 4 pad) — conflict-free frag LDS

__device__ __forceinline__ uint32_t tf32cvt(float x) {
    uint32_t o;
    asm("cvt.rna.tf32.f32 %0, %1;" : "=r"(o) : "f"(x));
    return o;
}

__device__ __forceinline__ void mma_tf32(float* d, const uint32_t* a, const uint32_t* b,
                                         const float* c) {
    asm volatile(
        "mma.sync.aligned.m16n8k8.row.col.f32.tf32.tf32.f32 "
        "{%0,%1,%2,%3}, {%4,%5,%6,%7}, {%8,%9}, {%10,%11,%12,%13};"
        : "=f"(d[0]), "=f"(d[1]), "=f"(d[2]), "=f"(d[3])
        : "r"(a[0]), "r"(a[1]), "r"(a[2]), "r"(a[3]),
          "r"(b[0]), "r"(b[1]),
          "f"(c[0]), "f"(c[1]), "f"(c[2]), "f"(c[3]));
}

__device__ __forceinline__ float4 ldg4z(const float* p, bool ok) {
    if (ok) return *reinterpret_cast<const float4*>(p);
    return make_float4(0.f, 0.f, 0.f, 0.f);
}

template <bool RELU>
__global__ __launch_bounds__(256)
void gemm_mma(const float* __restrict__ A1, const float* __restrict__ B1, int K1,
              const float* __restrict__ A2, const float* __restrict__ B2, int K2,
              const float* __restrict__ bias, float* __restrict__ C, int M) {
    __shared__ uint32_t As[2][BM * SPAD];
    __shared__ uint32_t Bs[2][BN * SPAD];

    int tid  = threadIdx.x;
    int wid  = tid >> 5;
    int lane = tid & 31;
    int wm   = wid >> 2;          // 0..1 : warp row
    int wn   = wid & 3;           // 0..3 : warp col
    int g    = lane >> 2;         // groupID (0..7)
    int tg   = lane & 3;          // thread-in-group (0..3)

    int m0 = blockIdx.x * BM;
    int n0 = blockIdx.y * BN;

    // staging: each thread moves 2 float4 for A and 2 for B per chunk
    int srow = tid >> 2;          // 0..63 (+64 on second pass)
    int skq  = tid & 3;           // float4 index within a 16-wide k-slice

    float acc[4][4][4];
    #pragma unroll
    for (int i = 0; i < 4; i++)
        #pragma unroll
        for (int j = 0; j < 4; j++)
            #pragma unroll
            for (int q = 0; q < 4; q++) acc[i][j][q] = 0.f;

    const int NC1 = K1 / BK;
    const int NC  = NC1 + K2 / BK;

    // ---- stage chunk 0 ----
    {
        const float* A = A1; const float* B = B1; int K = K1; int k0 = 0;
        #pragma unroll
        for (int l = 0; l < 2; l++) {
            int row = srow + l * 64;
            float4 va = ldg4z(A + (size_t)(m0 + row) * K + k0 + skq * 4, (m0 + row) < M);
            uint32_t* pa = &As[0][row * SPAD + skq * 4];
            pa[0] = tf32cvt(va.x); pa[1] = tf32cvt(va.y);
            pa[2] = tf32cvt(va.z); pa[3] = tf32cvt(va.w);
            float4 vb = *reinterpret_cast<const float4*>(B + (size_t)(n0 + row) * K + k0 + skq * 4);
            uint32_t* pb = &Bs[0][row * SPAD + skq * 4];
            pb[0] = tf32cvt(vb.x); pb[1] = tf32cvt(vb.y);
            pb[2] = tf32cvt(vb.z); pb[3] = tf32cvt(vb.w);
        }
    }
    __syncthreads();

    for (int c = 0; c < NC; c++) {
        int buf = c & 1;

        // prefetch chunk c+1 into registers (overlaps with mma below)
        float4 pa[2], pb[2];
        bool has_next = (c + 1) < NC;
        if (has_next) {
            int cn = c + 1;
            const float* A; const float* B; int K, k0;
            if (cn < NC1) { A = A1; B = B1; K = K1; k0 = cn * BK; }
            else          { A = A2; B = B2; K = K2; k0 = (cn - NC1) * BK; }
            #pragma unroll
            for (int l = 0; l < 2; l++) {
                int row = srow + l * 64;
                pa[l] = ldg4z(A + (size_t)(m0 + row) * K + k0 + skq * 4, (m0 + row) < M);
                pb[l] = *reinterpret_cast<const float4*>(B + (size_t)(n0 + row) * K + k0 + skq * 4);
            }
        }

        // ---- mma over this chunk (BK=16 -> two k8 steps) ----
        #pragma unroll
        for (int k8 = 0; k8 < 2; k8++) {
            int kk = k8 * 8 + tg;
            uint32_t af[4][4], bf[4][2];
            #pragma unroll
            for (int i = 0; i < 4; i++) {
                int m = wm * 64 + i * 16 + g;
                af[i][0] = As[buf][m * SPAD + kk];
                af[i][1] = As[buf][(m + 8) * SPAD + kk];
                af[i][2] = As[buf][m * SPAD + kk + 4];
                af[i][3] = As[buf][(m + 8) * SPAD + kk + 4];
            }
            #pragma unroll
            for (int j = 0; j < 4; j++) {
                int n = wn * 32 + j * 8 + g;
                bf[j][0] = Bs[buf][n * SPAD + kk];
                bf[j][1] = Bs[buf][n * SPAD + kk + 4];
            }
            #pragma unroll
            for (int i = 0; i < 4; i++)
                #pragma unroll
                for (int j = 0; j < 4; j++)
                    mma_tf32(acc[i][j], af[i], bf[j], acc[i][j]);
        }

        // ---- store prefetched chunk into the other buffer ----
        if (has_next) {
            int nbuf = buf ^ 1;
            #pragma unroll
            for (int l = 0; l < 2; l++) {
                int row = srow + l * 64;
                uint32_t* qa = &As[nbuf][row * SPAD + skq * 4];
                qa[0] = tf32cvt(pa[l].x); qa[1] = tf32cvt(pa[l].y);
                qa[2] = tf32cvt(pa[l].z); qa[3] = tf32cvt(pa[l].w);
                uint32_t* qb = &Bs[nbuf][row * SPAD + skq * 4];
                qb[0] = tf32cvt(pb[l].x); qb[1] = tf32cvt(pb[l].y);
                qb[2] = tf32cvt(pb[l].z); qb[3] = tf32cvt(pb[l].w);
            }
        }
        __syncthreads();
    }

    // ---- epilogue: c0,c1 -> (row g, cols 2tg,2tg+1); c2,c3 -> row g+8 ----
    #pragma unroll
    for (int i = 0; i < 4; i++) {
        int m = m0 + wm * 64 + i * 16 + g;
        #pragma unroll
        for (int j = 0; j < 4; j++) {
            int n = n0 + wn * 32 + j * 8 + 2 * tg;
            float bx = bias[n], by = bias[n + 1];
            if (m < M) {
                float2 v;
                v.x = acc[i][j][0] + bx;
                v.y = acc[i][j][1] + by;
                if (RELU) { v.x = fmaxf(v.x, 0.f); v.y = fmaxf(v.y, 0.f); }
                *reinterpret_cast<float2*>(C + (size_t)m * 256 + n) = v;
            }
            if (m + 8 < M) {
                float2 v;
                v.x = acc[i][j][2] + bx;
                v.y = acc[i][j][3] + by;
                if (RELU) { v.x = fmaxf(v.x, 0.f); v.y = fmaxf(v.y, 0.f); }
                *reinterpret_cast<float2*>(C + (size_t)(m + 8) * 256 + n) = v;
            }
        }
    }
}

// ---------------- heads: out1 = h@Wh1^T + bh1 (4), out2 = h@Wh2^T + bh2 (3) ----------------
__global__ void heads_kernel(const float* __restrict__ h,
                             const float* __restrict__ Wh1, const float* __restrict__ bh1,
                             const float* __restrict__ Wh2, const float* __restrict__ bh2,
                             float* __restrict__ out1, float* __restrict__ out2) {
    int node = blockIdx.x * (blockDim.x >> 5) + (threadIdx.x >> 5);
    if (node >= N_NODES) return;
    int lane = threadIdx.x & 31;
    const float4* row = reinterpret_cast<const float4*>(h + (size_t)node * HID);
    float4 r0 = row[lane];
    float4 r1 = row[lane + 32];
    float s[7];
    #pragma unroll
    for (int o = 0; o < 7; o++) {
        const float* w = (o < 4) ? (Wh1 + o * HID) : (Wh2 + (o - 4) * HID);
        const float4* wr = reinterpret_cast<const float4*>(w);
        float4 w0 = wr[lane];
        float4 w1 = wr[lane + 32];
        s[o] = r0.x * w0.x + r0.y * w0.y + r0.z * w0.z + r0.w * w0.w
             + r1.x * w1.x + r1.y * w1.y + r1.z * w1.z + r1.w * w1.w;
    }
    #pragma unroll
    for (int o = 0; o < 7; o++)
        #pragma unroll
        for (int d = 16; d > 0; d >>= 1)
            s[o] += __shfl_down_sync(0xffffffffu, s[o], d);
    if (lane == 0) {
        #pragma unroll
        for (int o = 0; o < 4; o++) out1[(size_t)node * 4 + o] = s[o] + bh1[o];
        #pragma unroll
        for (int o = 0; o < 3; o++) out2[(size_t)node * 3 + o] = s[4 + o] + bh2[o];
    }
}

// ---------------- launch ----------------
extern "C" void kernel_launch(void* const* d_in, const int* in_sizes, int n_in,
                              void* d_out, int out_size) {
    const float* x   = (const float*)d_in[0];
    const int*   ei  = (const int*)  d_in[1];
    const float* W1l = (const float*)d_in[2];
    const float* b1l = (const float*)d_in[3];
    const float* W1r = (const float*)d_in[4];
    const float* W2l = (const float*)d_in[5];
    const float* b2l = (const float*)d_in[6];
    const float* W2r = (const float*)d_in[7];
    const float* Wh1 = (const float*)d_in[8];
    const float* bh1 = (const float*)d_in[9];
    const float* Wh2 = (const float*)d_in[10];
    const float* bh2 = (const float*)d_in[11];

    float* out  = (float*)d_out;
    float* out1 = out;                                  // [N,4]
    float* out2 = out + (size_t)N_NODES * 4;            // [N,3]
    float* hout = out + (size_t)N_NODES * 7;            // [N,256]

    const int* src = ei;             // edge_index[0]
    const int* dst = ei + N_EDGES;   // edge_index[1]

    void *p_deg, *p_cur, *p_agg1, *p_h1, *p_agg2;
    cudaGetSymbolAddress(&p_deg,  g_deg);
    cudaGetSymbolAddress(&p_cur,  g_cur);
    cudaGetSymbolAddress(&p_agg1, g_agg1);
    cudaGetSymbolAddress(&p_h1,   g_h1);
    cudaGetSymbolAddress(&p_agg2, g_agg2);

    cudaMemsetAsync(p_deg, 0, N_NODES * sizeof(int));
    cudaMemsetAsync(p_cur, 0, N_NODES * sizeof(int));

    count_kernel<<<(N_EDGES + 255) / 256, 256>>>(dst);
    scan_kernel<<<1, 1024>>>();
    fill_kernel<<<(N_EDGES + 255) / 256, 256>>>(src, dst);

    dim3 gg((N_NODES + BM - 1) / BM, 2);   // 391 x 2

    // layer 1: h1 = relu(agg1 @ W1l^T + x @ W1r^T + b1l)
    agg_kernel<F_IN><<<(N_NODES + 7) / 8, 256>>>(x, (float*)p_agg1);
    gemm_mma<true><<<gg, 256>>>((const float*)p_agg1, W1l, F_IN, x, W1r, F_IN,
                                b1l, (float*)p_h1, N_NODES);

    // layer 2: hout = agg2 @ W2l^T + h1 @ W2r^T + b2l
    agg_kernel<HID><<<(N_NODES + 7) / 8, 256>>>((const float*)p_h1, (float*)p_agg2);
    gemm_mma<false><<<gg, 256>>>((const float*)p_agg2, W2l, HID, (const float*)p_h1, W2r, HID,
                                 b2l, hout, N_NODES);

    // heads
    heads_kernel<<<(N_NODES + 7) / 8, 256>>>(hout, Wh1, bh1, Wh2, bh2, out1, out2);
}

// round 4
// speedup vs baseline: 2.0022x; 1.0843x over previous
#include <cuda_runtime.h>
#include <cstdint>

#define N_NODES 50000
#define N_EDGES 800000
#define F_IN    128
#define HID     256

// ---------------- scratch (device globals; no allocation allowed) ----------------
__device__ int   g_deg[N_NODES];
__device__ int   g_off[N_NODES + 1];
__device__ int   g_cur[N_NODES];
__device__ int   g_csr[N_EDGES];
__device__ float g_agg1[(size_t)N_NODES * F_IN];
__device__ float g_h1  [(size_t)N_NODES * HID];
__device__ float g_agg2[(size_t)N_NODES * HID];

// ---------------- CSR build ----------------
__global__ void count_kernel(const int* __restrict__ dst) {
    int e = blockIdx.x * blockDim.x + threadIdx.x;
    if (e < N_EDGES) atomicAdd(&g_deg[dst[e]], 1);
}

__global__ void scan_kernel() {
    __shared__ int part[1024];
    int tid = threadIdx.x;
    const int chunk = (N_NODES + 1023) / 1024;
    int s = tid * chunk;
    int e = min(s + chunk, N_NODES);
    int sum = 0;
    for (int i = s; i < e; i++) sum += g_deg[i];
    part[tid] = sum;
    __syncthreads();
    #pragma unroll
    for (int o = 1; o < 1024; o <<= 1) {
        int add = (tid >= o) ? part[tid - o] : 0;
        __syncthreads();
        part[tid] += add;
        __syncthreads();
    }
    int run = part[tid] - sum;  // exclusive base
    for (int i = s; i < e; i++) { g_off[i] = run; run += g_deg[i]; }
    if (tid == 1023) g_off[N_NODES] = part[1023];
}

__global__ void fill_kernel(const int* __restrict__ src, const int* __restrict__ dst) {
    int e = blockIdx.x * blockDim.x + threadIdx.x;
    if (e >= N_EDGES) return;
    int d = dst[e];
    int pos = g_off[d] + atomicAdd(&g_cur[d], 1);
    g_csr[pos] = src[e];
}

// ---------------- mean aggregation: one warp per node ----------------
template <int F>
__global__ void agg_kernel(const float* __restrict__ feat, float* __restrict__ out) {
    int node = blockIdx.x * (blockDim.x >> 5) + (threadIdx.x >> 5);
    if (node >= N_NODES) return;
    int lane = threadIdx.x & 31;
    constexpr int V = F / 128;   // float4 chunks per lane
    float4 acc[V];
    #pragma unroll
    for (int v = 0; v < V; v++) acc[v] = make_float4(0.f, 0.f, 0.f, 0.f);
    int s = g_off[node], e = g_off[node + 1];
    for (int i = s; i < e; i++) {
        int src = g_csr[i];
        const float4* row = reinterpret_cast<const float4*>(feat + (size_t)src * F);
        #pragma unroll
        for (int v = 0; v < V; v++) {
            float4 t = row[lane + 32 * v];
            acc[v].x += t.x; acc[v].y += t.y; acc[v].z += t.z; acc[v].w += t.w;
        }
    }
    float inv = (e > s) ? 1.0f / (float)(e - s) : 0.0f;
    float4* orow = reinterpret_cast<float4*>(out + (size_t)node * F);
    #pragma unroll
    for (int v = 0; v < V; v++) {
        acc[v].x *= inv; acc[v].y *= inv; acc[v].z *= inv; acc[v].w *= inv;
        orow[lane + 32 * v] = acc[v];
    }
}

// ======================= tf32 mma.sync dual GEMM v2 =======================
// C[M, 256] = act( A1[M,K1] * B1[256,K1]^T + A2[M,K2] * B2[256,K2]^T + bias )
// CTA tile 128x256 (grid = M-tiles, full N per CTA), BK=32, 512 threads.
// cp.async double-buffered fp32 smem; tf32 cvt at fragment load (RNA).

#define GBM 128
#define GBN 256
#define GBK 32
#define GSP 36               // smem row stride in words (32 data + 4 pad)
#define GTHREADS 512

#define A_WORDS (GBM * GSP)          // 4608
#define B_WORDS (GBN * GSP)          // 9216
#define SMEM_WORDS (2 * A_WORDS + 2 * B_WORDS)   // 27648
#define GEMM_SMEM_BYTES (SMEM_WORDS * 4)         // 110592

__device__ __forceinline__ uint32_t tf32cvt(float x) {
    uint32_t o;
    asm("cvt.rna.tf32.f32 %0, %1;" : "=r"(o) : "f"(x));
    return o;
}

__device__ __forceinline__ void mma_tf32(float* d, const uint32_t* a, const uint32_t* b,
                                         const float* c) {
    asm volatile(
        "mma.sync.aligned.m16n8k8.row.col.f32.tf32.tf32.f32 "
        "{%0,%1,%2,%3}, {%4,%5,%6,%7}, {%8,%9}, {%10,%11,%12,%13};"
        : "=f"(d[0]), "=f"(d[1]), "=f"(d[2]), "=f"(d[3])
        : "r"(a[0]), "r"(a[1]), "r"(a[2]), "r"(a[3]),
          "r"(b[0]), "r"(b[1]),
          "f"(c[0]), "f"(c[1]), "f"(c[2]), "f"(c[3]));
}

__device__ __forceinline__ void cp16(uint32_t dst, const float* src, bool ok) {
    int sz = ok ? 16 : 0;
    asm volatile("cp.async.cg.shared.global [%0], [%1], 16, %2;"
                 :: "r"(dst), "l"(src), "r"(sz));
}
#define CP_COMMIT() asm volatile("cp.async.commit_group;" ::: "memory")
#define CP_WAIT(n)  asm volatile("cp.async.wait_group %0;" :: "n"(n) : "memory")

template <bool RELU>
__global__ __launch_bounds__(GTHREADS)
void gemm_mma2(const float* __restrict__ A1, const float* __restrict__ B1, int K1,
               const float* __restrict__ A2, const float* __restrict__ B2, int K2,
               const float* __restrict__ bias, float* __restrict__ C, int M) {
    extern __shared__ float gsm[];
    uint32_t sbase;
    asm("{ .reg .u64 t; cvta.to.shared.u64 t, %1; cvt.u32.u64 %0, t; }"
        : "=r"(sbase) : "l"(gsm));

    int tid  = threadIdx.x;
    int wid  = tid >> 5;
    int lane = tid & 31;
    int wm   = wid & 3;           // warp row: 32-row strip
    int wn   = wid >> 2;          // warp col: 64-col strip
    int g    = lane >> 2;         // groupID (0..7)
    int tg   = lane & 3;          // thread-in-group (0..3)

    int m0 = blockIdx.x * GBM;

    const int NC1 = K1 / GBK;
    const int NC  = NC1 + K2 / GBK;

    float acc[2][8][4];
    #pragma unroll
    for (int i = 0; i < 2; i++)
        #pragma unroll
        for (int j = 0; j < 8; j++)
            #pragma unroll
            for (int q = 0; q < 4; q++) acc[i][j][q] = 0.f;

    // stage chunk c into buffer buf
    auto stage = [&](int c, int buf) {
        const float* A; const float* B; int K, k0;
        if (c < NC1) { A = A1; B = B1; K = K1; k0 = c * GBK; }
        else         { A = A2; B = B2; K = K2; k0 = (c - NC1) * GBK; }
        uint32_t abase = sbase + (buf * A_WORDS) * 4;
        uint32_t bbase = sbase + (2 * A_WORDS + buf * B_WORDS) * 4;
        // A: 128 rows x 8 float4 = 1024 -> 2/thread
        #pragma unroll
        for (int l = 0; l < 2; l++) {
            int idx = tid + l * GTHREADS;
            int row = idx >> 3;
            int q   = idx & 7;
            cp16(abase + (row * GSP + q * 4) * 4,
                 A + (size_t)(m0 + row) * K + k0 + q * 4,
                 (m0 + row) < M);
        }
        // B: 256 rows x 8 float4 = 2048 -> 4/thread
        #pragma unroll
        for (int l = 0; l < 4; l++) {
            int idx = tid + l * GTHREADS;
            int row = idx >> 3;
            int q   = idx & 7;
            cp16(bbase + (row * GSP + q * 4) * 4,
                 B + (size_t)row * K + k0 + q * 4, true);
        }
    };

    stage(0, 0);
    CP_COMMIT();

    for (int c = 0; c < NC; c++) {
        int buf = c & 1;
        if (c + 1 < NC) {
            stage(c + 1, buf ^ 1);
            CP_COMMIT();
            CP_WAIT(1);
        } else {
            CP_WAIT(0);
        }
        __syncthreads();

        const float* As = gsm + buf * A_WORDS;
        const float* Bs = gsm + 2 * A_WORDS + buf * B_WORDS;

        #pragma unroll
        for (int k8 = 0; k8 < 4; k8++) {
            int kk = k8 * 8 + tg;
            uint32_t af[2][4], bf[8][2];
            #pragma unroll
            for (int i = 0; i < 2; i++) {
                int m = wm * 32 + i * 16 + g;
                af[i][0] = tf32cvt(As[m * GSP + kk]);
                af[i][1] = tf32cvt(As[(m + 8) * GSP + kk]);
                af[i][2] = tf32cvt(As[m * GSP + kk + 4]);
                af[i][3] = tf32cvt(As[(m + 8) * GSP + kk + 4]);
            }
            #pragma unroll
            for (int j = 0; j < 8; j++) {
                int n = wn * 64 + j * 8 + g;
                bf[j][0] = tf32cvt(Bs[n * GSP + kk]);
                bf[j][1] = tf32cvt(Bs[n * GSP + kk + 4]);
            }
            #pragma unroll
            for (int i = 0; i < 2; i++)
                #pragma unroll
                for (int j = 0; j < 8; j++)
                    mma_tf32(acc[i][j], af[i], bf[j], acc[i][j]);
        }
        __syncthreads();
    }

    // ---- epilogue ----
    #pragma unroll
    for (int i = 0; i < 2; i++) {
        int m = m0 + wm * 32 + i * 16 + g;
        #pragma unroll
        for (int j = 0; j < 8; j++) {
            int n = wn * 64 + j * 8 + 2 * tg;
            float bx = bias[n], by = bias[n + 1];
            if (m < M) {
                float2 v;
                v.x = acc[i][j][0] + bx;
                v.y = acc[i][j][1] + by;
                if (RELU) { v.x = fmaxf(v.x, 0.f); v.y = fmaxf(v.y, 0.f); }
                *reinterpret_cast<float2*>(C + (size_t)m * 256 + n) = v;
            }
            if (m + 8 < M) {
                float2 v;
                v.x = acc[i][j][2] + bx;
                v.y = acc[i][j][3] + by;
                if (RELU) { v.x = fmaxf(v.x, 0.f); v.y = fmaxf(v.y, 0.f); }
                *reinterpret_cast<float2*>(C + (size_t)(m + 8) * 256 + n) = v;
            }
        }
    }
}

// ---------------- heads: out1 = h@Wh1^T + bh1 (4), out2 = h@Wh2^T + bh2 (3) ----------------
__global__ void heads_kernel(const float* __restrict__ h,
                             const float* __restrict__ Wh1, const float* __restrict__ bh1,
                             const float* __restrict__ Wh2, const float* __restrict__ bh2,
                             float* __restrict__ out1, float* __restrict__ out2) {
    int node = blockIdx.x * (blockDim.x >> 5) + (threadIdx.x >> 5);
    if (node >= N_NODES) return;
    int lane = threadIdx.x & 31;
    const float4* row = reinterpret_cast<const float4*>(h + (size_t)node * HID);
    float4 r0 = row[lane];
    float4 r1 = row[lane + 32];
    float s[7];
    #pragma unroll
    for (int o = 0; o < 7; o++) {
        const float* w = (o < 4) ? (Wh1 + o * HID) : (Wh2 + (o - 4) * HID);
        const float4* wr = reinterpret_cast<const float4*>(w);
        float4 w0 = wr[lane];
        float4 w1 = wr[lane + 32];
        s[o] = r0.x * w0.x + r0.y * w0.y + r0.z * w0.z + r0.w * w0.w
             + r1.x * w1.x + r1.y * w1.y + r1.z * w1.z + r1.w * w1.w;
    }
    #pragma unroll
    for (int o = 0; o < 7; o++)
        #pragma unroll
        for (int d = 16; d > 0; d >>= 1)
            s[o] += __shfl_down_sync(0xffffffffu, s[o], d);
    if (lane == 0) {
        #pragma unroll
        for (int o = 0; o < 4; o++) out1[(size_t)node * 4 + o] = s[o] + bh1[o];
        #pragma unroll
        for (int o = 0; o < 3; o++) out2[(size_t)node * 3 + o] = s[4 + o] + bh2[o];
    }
}

// ---------------- launch ----------------
extern "C" void kernel_launch(void* const* d_in, const int* in_sizes, int n_in,
                              void* d_out, int out_size) {
    const float* x   = (const float*)d_in[0];
    const int*   ei  = (const int*)  d_in[1];
    const float* W1l = (const float*)d_in[2];
    const float* b1l = (const float*)d_in[3];
    const float* W1r = (const float*)d_in[4];
    const float* W2l = (const float*)d_in[5];
    const float* b2l = (const float*)d_in[6];
    const float* W2r = (const float*)d_in[7];
    const float* Wh1 = (const float*)d_in[8];
    const float* bh1 = (const float*)d_in[9];
    const float* Wh2 = (const float*)d_in[10];
    const float* bh2 = (const float*)d_in[11];

    float* out  = (float*)d_out;
    float* out1 = out;                                  // [N,4]
    float* out2 = out + (size_t)N_NODES * 4;            // [N,3]
    float* hout = out + (size_t)N_NODES * 7;            // [N,256]

    const int* src = ei;             // edge_index[0]
    const int* dst = ei + N_EDGES;   // edge_index[1]

    void *p_deg, *p_cur, *p_agg1, *p_h1, *p_agg2;
    cudaGetSymbolAddress(&p_deg,  g_deg);
    cudaGetSymbolAddress(&p_cur,  g_cur);
    cudaGetSymbolAddress(&p_agg1, g_agg1);
    cudaGetSymbolAddress(&p_h1,   g_h1);
    cudaGetSymbolAddress(&p_agg2, g_agg2);

    cudaFuncSetAttribute(gemm_mma2<true>,  cudaFuncAttributeMaxDynamicSharedMemorySize, GEMM_SMEM_BYTES);
    cudaFuncSetAttribute(gemm_mma2<false>, cudaFuncAttributeMaxDynamicSharedMemorySize, GEMM_SMEM_BYTES);

    cudaMemsetAsync(p_deg, 0, N_NODES * sizeof(int));
    cudaMemsetAsync(p_cur, 0, N_NODES * sizeof(int));

    count_kernel<<<(N_EDGES + 255) / 256, 256>>>(dst);
    scan_kernel<<<1, 1024>>>();
    fill_kernel<<<(N_EDGES + 255) / 256, 256>>>(src, dst);

    int gtiles = (N_NODES + GBM - 1) / GBM;   // 391

    // layer 1: h1 = relu(agg1 @ W1l^T + x @ W1r^T + b1l)
    agg_kernel<F_IN><<<(N_NODES + 7) / 8, 256>>>(x, (float*)p_agg1);
    gemm_mma2<true><<<gtiles, GTHREADS, GEMM_SMEM_BYTES>>>(
        (const float*)p_agg1, W1l, F_IN, x, W1r, F_IN, b1l, (float*)p_h1, N_NODES);

    // layer 2: hout = agg2 @ W2l^T + h1 @ W2r^T + b2l
    agg_kernel<HID><<<(N_NODES + 7) / 8, 256>>>((const float*)p_h1, (float*)p_agg2);
    gemm_mma2<false><<<gtiles, GTHREADS, GEMM_SMEM_BYTES>>>(
        (const float*)p_agg2, W2l, HID, (const float*)p_h1, W2r, HID, b2l, hout, N_NODES);

    // heads
    heads_kernel<<<(N_NODES + 7) / 8, 256>>>(hout, Wh1, bh1, Wh2, bh2, out1, out2);
}

// round 5
// speedup vs baseline: 2.0407x; 1.0192x over previous
#include <cuda_runtime.h>
#include <cstdint>

#define N_NODES 50000
#define N_EDGES 800000
#define F_IN    128
#define HID     256

// ---------------- scratch (device globals; no allocation allowed) ----------------
__device__ int   g_deg[N_NODES];
__device__ int   g_off[N_NODES + 1];
__device__ int   g_cur[N_NODES];
__device__ int   g_csr[N_EDGES];
__device__ float g_agg1[(size_t)N_NODES * F_IN];
__device__ float g_h1  [(size_t)N_NODES * HID];
__device__ float g_agg2[(size_t)N_NODES * HID];
__device__ float g_xr  [(size_t)N_NODES * F_IN];   // tf32-rounded x
__device__ float g_wr  [196608];                   // tf32-rounded W1l|W1r|W2l|W2r

#define W1L_OFF 0
#define W1R_OFF 32768
#define W2L_OFF 65536
#define W2R_OFF 131072

__device__ __forceinline__ uint32_t tf32cvt(float x) {
    uint32_t o;
    asm("cvt.rna.tf32.f32 %0, %1;" : "=r"(o) : "f"(x));
    return o;
}
__device__ __forceinline__ float tf32f(float x) { return __uint_as_float(tf32cvt(x)); }

// ---------------- prep: round x and weights to tf32 (float4-vectorized) ----------------
#define XN4 ((N_NODES * F_IN) / 4)      // 1,600,000
#define WN4 (196608 / 4)                // 49,152
__global__ void prep_round(const float* __restrict__ x,
                           const float* __restrict__ w1l, const float* __restrict__ w1r,
                           const float* __restrict__ w2l, const float* __restrict__ w2r) {
    int i = blockIdx.x * blockDim.x + threadIdx.x;
    if (i < XN4) {
        float4 v = reinterpret_cast<const float4*>(x)[i];
        v.x = tf32f(v.x); v.y = tf32f(v.y); v.z = tf32f(v.z); v.w = tf32f(v.w);
        reinterpret_cast<float4*>(g_xr)[i] = v;
        return;
    }
    int j = i - XN4;
    if (j >= WN4) return;
    int e = j * 4;
    const float* s;
    if      (e < W1R_OFF) s = w1l + (e - W1L_OFF);
    else if (e < W2L_OFF) s = w1r + (e - W1R_OFF);
    else if (e < W2R_OFF) s = w2l + (e - W2L_OFF);
    else                  s = w2r + (e - W2R_OFF);
    float4 v = *reinterpret_cast<const float4*>(s);
    v.x = tf32f(v.x); v.y = tf32f(v.y); v.z = tf32f(v.z); v.w = tf32f(v.w);
    reinterpret_cast<float4*>(g_wr)[j] = v;
}

// ---------------- CSR build ----------------
__global__ void count_kernel(const int* __restrict__ dst) {
    int e = blockIdx.x * blockDim.x + threadIdx.x;
    if (e < N_EDGES) atomicAdd(&g_deg[dst[e]], 1);
}

__global__ void scan_kernel() {
    __shared__ int part[1024];
    int tid = threadIdx.x;
    const int chunk = (N_NODES + 1023) / 1024;
    int s = tid * chunk;
    int e = min(s + chunk, N_NODES);
    int sum = 0;
    for (int i = s; i < e; i++) sum += g_deg[i];
    part[tid] = sum;
    __syncthreads();
    #pragma unroll
    for (int o = 1; o < 1024; o <<= 1) {
        int add = (tid >= o) ? part[tid - o] : 0;
        __syncthreads();
        part[tid] += add;
        __syncthreads();
    }
    int run = part[tid] - sum;  // exclusive base
    for (int i = s; i < e; i++) { g_off[i] = run; run += g_deg[i]; }
    if (tid == 1023) g_off[N_NODES] = part[1023];
}

__global__ void fill_kernel(const int* __restrict__ src, const int* __restrict__ dst) {
    int e = blockIdx.x * blockDim.x + threadIdx.x;
    if (e >= N_EDGES) return;
    int d = dst[e];
    int pos = g_off[d] + atomicAdd(&g_cur[d], 1);
    g_csr[pos] = src[e];
}

// ---------------- mean aggregation: one warp per node (tf32-rounded output) ----------------
template <int F>
__global__ void agg_kernel(const float* __restrict__ feat, float* __restrict__ out) {
    int node = blockIdx.x * (blockDim.x >> 5) + (threadIdx.x >> 5);
    if (node >= N_NODES) return;
    int lane = threadIdx.x & 31;
    constexpr int V = F / 128;   // float4 chunks per lane
    float4 acc[V];
    #pragma unroll
    for (int v = 0; v < V; v++) acc[v] = make_float4(0.f, 0.f, 0.f, 0.f);
    int s = g_off[node], e = g_off[node + 1];
    for (int i = s; i < e; i++) {
        int src = g_csr[i];
        const float4* row = reinterpret_cast<const float4*>(feat + (size_t)src * F);
        #pragma unroll
        for (int v = 0; v < V; v++) {
            float4 t = row[lane + 32 * v];
            acc[v].x += t.x; acc[v].y += t.y; acc[v].z += t.z; acc[v].w += t.w;
        }
    }
    float inv = (e > s) ? 1.0f / (float)(e - s) : 0.0f;
    float4* orow = reinterpret_cast<float4*>(out + (size_t)node * F);
    #pragma unroll
    for (int v = 0; v < V; v++) {
        acc[v].x = tf32f(acc[v].x * inv);
        acc[v].y = tf32f(acc[v].y * inv);
        acc[v].z = tf32f(acc[v].z * inv);
        acc[v].w = tf32f(acc[v].w * inv);
        orow[lane + 32 * v] = acc[v];
    }
}

// ======================= tf32 mma.sync dual GEMM v3 =======================
// All operands pre-rounded to tf32 -> NO cvt anywhere in the hot loop.
// C[M, 256] = act( A1[M,K1] * B1[256,K1]^T + A2[M,K2] * B2[256,K2]^T + bias )
// CTA tile 128x256, BK=32, 512 threads, cp.async double-buffered.

#define GBM 128
#define GBN 256
#define GBK 32
#define GSP 36               // smem row stride in words (32 data + 4 pad)
#define GTHREADS 512

#define A_WORDS (GBM * GSP)          // 4608
#define B_WORDS (GBN * GSP)          // 9216
#define SMEM_WORDS (2 * A_WORDS + 2 * B_WORDS)   // 27648
#define GEMM_SMEM_BYTES (SMEM_WORDS * 4)         // 110592

__device__ __forceinline__ void mma_tf32(float* d, const uint32_t* a, const uint32_t* b,
                                         const float* c) {
    asm volatile(
        "mma.sync.aligned.m16n8k8.row.col.f32.tf32.tf32.f32 "
        "{%0,%1,%2,%3}, {%4,%5,%6,%7}, {%8,%9}, {%10,%11,%12,%13};"
        : "=f"(d[0]), "=f"(d[1]), "=f"(d[2]), "=f"(d[3])
        : "r"(a[0]), "r"(a[1]), "r"(a[2]), "r"(a[3]),
          "r"(b[0]), "r"(b[1]),
          "f"(c[0]), "f"(c[1]), "f"(c[2]), "f"(c[3]));
}

__device__ __forceinline__ void cp16(uint32_t dst, const float* src, bool ok) {
    int sz = ok ? 16 : 0;
    asm volatile("cp.async.cg.shared.global [%0], [%1], 16, %2;"
                 :: "r"(dst), "l"(src), "r"(sz));
}
#define CP_COMMIT() asm volatile("cp.async.commit_group;" ::: "memory")
#define CP_WAIT(n)  asm volatile("cp.async.wait_group %0;" :: "n"(n) : "memory")

template <bool RELU, bool ROUND_OUT>
__global__ __launch_bounds__(GTHREADS)
void gemm_mma3(const float* __restrict__ A1, const float* __restrict__ B1, int K1,
               const float* __restrict__ A2, const float* __restrict__ B2, int K2,
               const float* __restrict__ bias, float* __restrict__ C, int M) {
    extern __shared__ float gsm[];
    uint32_t sbase;
    asm("{ .reg .u64 t; cvta.to.shared.u64 t, %1; cvt.u32.u64 %0, t; }"
        : "=r"(sbase) : "l"(gsm));

    int tid  = threadIdx.x;
    int wid  = tid >> 5;
    int lane = tid & 31;
    int wm   = wid & 3;           // warp row: 32-row strip
    int wn   = wid >> 2;          // warp col: 64-col strip
    int g    = lane >> 2;         // groupID (0..7)
    int tg   = lane & 3;          // thread-in-group (0..3)

    int m0 = blockIdx.x * GBM;

    const int NC1 = K1 / GBK;
    const int NC  = NC1 + K2 / GBK;

    float acc[2][8][4];
    #pragma unroll
    for (int i = 0; i < 2; i++)
        #pragma unroll
        for (int j = 0; j < 8; j++)
            #pragma unroll
            for (int q = 0; q < 4; q++) acc[i][j][q] = 0.f;

    auto stage = [&](int c, int buf) {
        const float* A; const float* B; int K, k0;
        if (c < NC1) { A = A1; B = B1; K = K1; k0 = c * GBK; }
        else         { A = A2; B = B2; K = K2; k0 = (c - NC1) * GBK; }
        uint32_t abase = sbase + (buf * A_WORDS) * 4;
        uint32_t bbase = sbase + (2 * A_WORDS + buf * B_WORDS) * 4;
        #pragma unroll
        for (int l = 0; l < 2; l++) {
            int idx = tid + l * GTHREADS;
            int row = idx >> 3;
            int q   = idx & 7;
            cp16(abase + (row * GSP + q * 4) * 4,
                 A + (size_t)(m0 + row) * K + k0 + q * 4,
                 (m0 + row) < M);
        }
        #pragma unroll
        for (int l = 0; l < 4; l++) {
            int idx = tid + l * GTHREADS;
            int row = idx >> 3;
            int q   = idx & 7;
            cp16(bbase + (row * GSP + q * 4) * 4,
                 B + (size_t)row * K + k0 + q * 4, true);
        }
    };

    stage(0, 0);
    CP_COMMIT();

    const uint32_t* usm = reinterpret_cast<const uint32_t*>(gsm);

    for (int c = 0; c < NC; c++) {
        int buf = c & 1;
        if (c + 1 < NC) {
            stage(c + 1, buf ^ 1);
            CP_COMMIT();
            CP_WAIT(1);
        } else {
            CP_WAIT(0);
        }
        __syncthreads();

        const uint32_t* As = usm + buf * A_WORDS;
        const uint32_t* Bs = usm + 2 * A_WORDS + buf * B_WORDS;

        #pragma unroll
        for (int k8 = 0; k8 < 4; k8++) {
            int kk = k8 * 8 + tg;
            uint32_t af[2][4], bf[8][2];
            #pragma unroll
            for (int i = 0; i < 2; i++) {
                int m = wm * 32 + i * 16 + g;
                af[i][0] = As[m * GSP + kk];
                af[i][1] = As[(m + 8) * GSP + kk];
                af[i][2] = As[m * GSP + kk + 4];
                af[i][3] = As[(m + 8) * GSP + kk + 4];
            }
            #pragma unroll
            for (int j = 0; j < 8; j++) {
                int n = wn * 64 + j * 8 + g;
                bf[j][0] = Bs[n * GSP + kk];
                bf[j][1] = Bs[n * GSP + kk + 4];
            }
            #pragma unroll
            for (int i = 0; i < 2; i++)
                #pragma unroll
                for (int j = 0; j < 8; j++)
                    mma_tf32(acc[i][j], af[i], bf[j], acc[i][j]);
        }
        __syncthreads();
    }

    // ---- epilogue ----
    #pragma unroll
    for (int i = 0; i < 2; i++) {
        int m = m0 + wm * 32 + i * 16 + g;
        #pragma unroll
        for (int j = 0; j < 8; j++) {
            int n = wn * 64 + j * 8 + 2 * tg;
            float bx = bias[n], by = bias[n + 1];
            if (m < M) {
                float2 v;
                v.x = acc[i][j][0] + bx;
                v.y = acc[i][j][1] + by;
                if (RELU) { v.x = fmaxf(v.x, 0.f); v.y = fmaxf(v.y, 0.f); }
                if (ROUND_OUT) { v.x = tf32f(v.x); v.y = tf32f(v.y); }
                *reinterpret_cast<float2*>(C + (size_t)m * 256 + n) = v;
            }
            if (m + 8 < M) {
                float2 v;
                v.x = acc[i][j][2] + bx;
                v.y = acc[i][j][3] + by;
                if (RELU) { v.x = fmaxf(v.x, 0.f); v.y = fmaxf(v.y, 0.f); }
                if (ROUND_OUT) { v.x = tf32f(v.x); v.y = tf32f(v.y); }
                *reinterpret_cast<float2*>(C + (size_t)(m + 8) * 256 + n) = v;
            }
        }
    }
}

// ---------------- heads: out1 = h@Wh1^T + bh1 (4), out2 = h@Wh2^T + bh2 (3) ----------------
__global__ void heads_kernel(const float* __restrict__ h,
                             const float* __restrict__ Wh1, const float* __restrict__ bh1,
                             const float* __restrict__ Wh2, const float* __restrict__ bh2,
                             float* __restrict__ out1, float* __restrict__ out2) {
    int node = blockIdx.x * (blockDim.x >> 5) + (threadIdx.x >> 5);
    if (node >= N_NODES) return;
    int lane = threadIdx.x & 31;
    const float4* row = reinterpret_cast<const float4*>(h + (size_t)node * HID);
    float4 r0 = row[lane];
    float4 r1 = row[lane + 32];
    float s[7];
    #pragma unroll
    for (int o = 0; o < 7; o++) {
        const float* w = (o < 4) ? (Wh1 + o * HID) : (Wh2 + (o - 4) * HID);
        const float4* wr = reinterpret_cast<const float4*>(w);
        float4 w0 = wr[lane];
        float4 w1 = wr[lane + 32];
        s[o] = r0.x * w0.x + r0.y * w0.y + r0.z * w0.z + r0.w * w0.w
             + r1.x * w1.x + r1.y * w1.y + r1.z * w1.z + r1.w * w1.w;
    }
    #pragma unroll
    for (int o = 0; o < 7; o++)
        #pragma unroll
        for (int d = 16; d > 0; d >>= 1)
            s[o] += __shfl_down_sync(0xffffffffu, s[o], d);
    if (lane == 0) {
        #pragma unroll
        for (int o = 0; o < 4; o++) out1[(size_t)node * 4 + o] = s[o] + bh1[o];
        #pragma unroll
        for (int o = 0; o < 3; o++) out2[(size_t)node * 3 + o] = s[4 + o] + bh2[o];
    }
}

// ---------------- launch ----------------
extern "C" void kernel_launch(void* const* d_in, const int* in_sizes, int n_in,
                              void* d_out, int out_size) {
    const float* x   = (const float*)d_in[0];
    const int*   ei  = (const int*)  d_in[1];
    const float* W1l = (const float*)d_in[2];
    const float* b1l = (const float*)d_in[3];
    const float* W1r = (const float*)d_in[4];
    const float* W2l = (const float*)d_in[5];
    const float* b2l = (const float*)d_in[6];
    const float* W2r = (const float*)d_in[7];
    const float* Wh1 = (const float*)d_in[8];
    const float* bh1 = (const float*)d_in[9];
    const float* Wh2 = (const float*)d_in[10];
    const float* bh2 = (const float*)d_in[11];

    float* out  = (float*)d_out;
    float* out1 = out;                                  // [N,4]
    float* out2 = out + (size_t)N_NODES * 4;            // [N,3]
    float* hout = out + (size_t)N_NODES * 7;            // [N,256]

    const int* src = ei;             // edge_index[0]
    const int* dst = ei + N_EDGES;   // edge_index[1]

    void *p_deg, *p_cur, *p_agg1, *p_h1, *p_agg2, *p_xr, *p_wr;
    cudaGetSymbolAddress(&p_deg,  g_deg);
    cudaGetSymbolAddress(&p_cur,  g_cur);
    cudaGetSymbolAddress(&p_agg1, g_agg1);
    cudaGetSymbolAddress(&p_h1,   g_h1);
    cudaGetSymbolAddress(&p_agg2, g_agg2);
    cudaGetSymbolAddress(&p_xr,   g_xr);
    cudaGetSymbolAddress(&p_wr,   g_wr);
    const float* xr = (const float*)p_xr;
    const float* wr = (const float*)p_wr;

    cudaFuncSetAttribute(gemm_mma3<true, true>,   cudaFuncAttributeMaxDynamicSharedMemorySize, GEMM_SMEM_BYTES);
    cudaFuncSetAttribute(gemm_mma3<false, false>, cudaFuncAttributeMaxDynamicSharedMemorySize, GEMM_SMEM_BYTES);

    cudaMemsetAsync(p_deg, 0, N_NODES * sizeof(int));
    cudaMemsetAsync(p_cur, 0, N_NODES * sizeof(int));

    prep_round<<<(XN4 + WN4 + 255) / 256, 256>>>(x, W1l, W1r, W2l, W2r);

    count_kernel<<<(N_EDGES + 255) / 256, 256>>>(dst);
    scan_kernel<<<1, 1024>>>();
    fill_kernel<<<(N_EDGES + 255) / 256, 256>>>(src, dst);

    int gtiles = (N_NODES + GBM - 1) / GBM;   // 391

    // layer 1: h1 = relu(agg1 @ W1l^T + x @ W1r^T + b1l)   [h1 stored tf32-rounded]
    agg_kernel<F_IN><<<(N_NODES + 7) / 8, 256>>>(xr, (float*)p_agg1);
    gemm_mma3<true, true><<<gtiles, GTHREADS, GEMM_SMEM_BYTES>>>(
        (const float*)p_agg1, wr + W1L_OFF, F_IN, xr, wr + W1R_OFF, F_IN,
        b1l, (float*)p_h1, N_NODES);

    // layer 2: hout = agg2 @ W2l^T + h1 @ W2r^T + b2l      [hout exact fp32]
    agg_kernel<HID><<<(N_NODES + 7) / 8, 256>>>((const float*)p_h1, (float*)p_agg2);
    gemm_mma3<false, false><<<gtiles, GTHREADS, GEMM_SMEM_BYTES>>>(
        (const float*)p_agg2, wr + W2L_OFF, HID, (const float*)p_h1, wr + W2R_OFF, HID,
        b2l, hout, N_NODES);

    // heads
    heads_kernel<<<(N_NODES + 7) / 8, 256>>>(hout, Wh1, bh1, Wh2, bh2, out1, out2);
}

// round 6
// speedup vs baseline: 2.4223x; 1.1870x over previous
#include <cuda_runtime.h>
#include <cstdint>

#define N_NODES 50000
#define N_EDGES 800000
#define F_IN    128
#define HID     256

// ---------------- scratch (device globals; no allocation allowed) ----------------
__device__ int   g_deg[N_NODES];
__device__ int   g_off[N_NODES + 1];
__device__ int   g_cur[N_NODES];
__device__ int   g_csr[N_EDGES];
__device__ int   g_bsum[256];
__device__ float g_agg1[(size_t)N_NODES * F_IN];
__device__ float g_h1  [(size_t)N_NODES * HID];
__device__ float g_agg2[(size_t)N_NODES * HID];
__device__ float g_xr  [(size_t)N_NODES * F_IN];   // tf32-rounded x
__device__ float g_wr  [196608];                   // tf32-rounded W1l|W1r|W2l|W2r

#define W1L_OFF 0
#define W1R_OFF 32768
#define W2L_OFF 65536
#define W2R_OFF 131072

__device__ __forceinline__ uint32_t tf32cvt(float x) {
    uint32_t o;
    asm("cvt.rna.tf32.f32 %0, %1;" : "=r"(o) : "f"(x));
    return o;
}
__device__ __forceinline__ float tf32f(float x) { return __uint_as_float(tf32cvt(x)); }

// ---------------- prep: round x and weights to tf32 (float4-vectorized) ----------------
#define XN4 ((N_NODES * F_IN) / 4)      // 1,600,000
#define WN4 (196608 / 4)                // 49,152
__global__ void prep_round(const float* __restrict__ x,
                           const float* __restrict__ w1l, const float* __restrict__ w1r,
                           const float* __restrict__ w2l, const float* __restrict__ w2r) {
    int i = blockIdx.x * blockDim.x + threadIdx.x;
    if (i < XN4) {
        float4 v = reinterpret_cast<const float4*>(x)[i];
        v.x = tf32f(v.x); v.y = tf32f(v.y); v.z = tf32f(v.z); v.w = tf32f(v.w);
        reinterpret_cast<float4*>(g_xr)[i] = v;
        return;
    }
    int j = i - XN4;
    if (j >= WN4) return;
    int e = j * 4;
    const float* s;
    if      (e < W1R_OFF) s = w1l + (e - W1L_OFF);
    else if (e < W2L_OFF) s = w1r + (e - W1R_OFF);
    else if (e < W2R_OFF) s = w2l + (e - W2L_OFF);
    else                  s = w2r + (e - W2R_OFF);
    float4 v = *reinterpret_cast<const float4*>(s);
    v.x = tf32f(v.x); v.y = tf32f(v.y); v.z = tf32f(v.z); v.w = tf32f(v.w);
    reinterpret_cast<float4*>(g_wr)[j] = v;
}

// ---------------- CSR build ----------------
__global__ void count_kernel(const int* __restrict__ dst) {
    int t = blockIdx.x * blockDim.x + threadIdx.x;
    int e0 = t * 4;
    if (e0 >= N_EDGES) return;
    int4 d = *reinterpret_cast<const int4*>(dst + e0);   // N_EDGES % 4 == 0
    atomicAdd(&g_deg[d.x], 1);
    atomicAdd(&g_deg[d.y], 1);
    atomicAdd(&g_deg[d.z], 1);
    atomicAdd(&g_deg[d.w], 1);
}

// 3-kernel parallel exclusive scan of g_deg -> g_off
#define SCAN_BLOCKS 196
__device__ __forceinline__ int warp_incl_scan(int v, int lane) {
    #pragma unroll
    for (int o = 1; o < 32; o <<= 1) {
        int t = __shfl_up_sync(0xffffffffu, v, o);
        if (lane >= o) v += t;
    }
    return v;
}

__global__ void scan1_kernel() {   // grid=196, block=256: local exclusive scan + block sums
    __shared__ int ws[8];
    int tid = threadIdx.x, lane = tid & 31, w = tid >> 5;
    int i = blockIdx.x * 256 + tid;
    int v = (i < N_NODES) ? g_deg[i] : 0;
    int inc = warp_incl_scan(v, lane);
    if (lane == 31) ws[w] = inc;
    __syncthreads();
    if (w == 0) {
        int t = (lane < 8) ? ws[lane] : 0;
        t = warp_incl_scan(t, lane);
        if (lane < 8) ws[lane] = t;
    }
    __syncthreads();
    int base = (w > 0) ? ws[w - 1] : 0;
    if (i < N_NODES) g_off[i] = base + inc - v;
    if (tid == 255) g_bsum[blockIdx.x] = ws[7];
}

__global__ void scan2_kernel() {   // 1 block 256: spine scan
    __shared__ int ws[8];
    int tid = threadIdx.x, lane = tid & 31, w = tid >> 5;
    int v = (tid < SCAN_BLOCKS) ? g_bsum[tid] : 0;
    int inc = warp_incl_scan(v, lane);
    if (lane == 31) ws[w] = inc;
    __syncthreads();
    if (w == 0) {
        int t = (lane < 8) ? ws[lane] : 0;
        t = warp_incl_scan(t, lane);
        if (lane < 8) ws[lane] = t;
    }
    __syncthreads();
    int base = (w > 0) ? ws[w - 1] : 0;
    if (tid < SCAN_BLOCKS) g_bsum[tid] = base + inc - v;   // exclusive
    if (tid == 255) g_off[N_NODES] = ws[7];                // total = N_EDGES
}

__global__ void scan3_kernel() {   // grid=196, block=256: add block offsets
    int i = blockIdx.x * 256 + threadIdx.x;
    if (i < N_NODES) g_off[i] += g_bsum[blockIdx.x];
}

__global__ void fill_kernel(const int* __restrict__ src, const int* __restrict__ dst) {
    int t = blockIdx.x * blockDim.x + threadIdx.x;
    int e0 = t * 4;
    if (e0 >= N_EDGES) return;
    int4 d = *reinterpret_cast<const int4*>(dst + e0);
    int4 s = *reinterpret_cast<const int4*>(src + e0);
    g_csr[g_off[d.x] + atomicAdd(&g_cur[d.x], 1)] = s.x;
    g_csr[g_off[d.y] + atomicAdd(&g_cur[d.y], 1)] = s.y;
    g_csr[g_off[d.z] + atomicAdd(&g_cur[d.z], 1)] = s.z;
    g_csr[g_off[d.w] + atomicAdd(&g_cur[d.w], 1)] = s.w;
}

// ---------------- mean aggregation: one warp per node, 2-edge unroll ----------------
template <int F>
__global__ void agg_kernel(const float* __restrict__ feat, float* __restrict__ out) {
    int node = blockIdx.x * (blockDim.x >> 5) + (threadIdx.x >> 5);
    if (node >= N_NODES) return;
    int lane = threadIdx.x & 31;
    constexpr int V = F / 128;   // float4 chunks per lane
    float4 acc0[V], acc1[V];
    #pragma unroll
    for (int v = 0; v < V; v++) {
        acc0[v] = make_float4(0.f, 0.f, 0.f, 0.f);
        acc1[v] = make_float4(0.f, 0.f, 0.f, 0.f);
    }
    int s = g_off[node], e = g_off[node + 1];
    int i = s;
    for (; i + 1 < e; i += 2) {
        int s0 = g_csr[i];
        int s1 = g_csr[i + 1];
        const float4* r0 = reinterpret_cast<const float4*>(feat + (size_t)s0 * F);
        const float4* r1 = reinterpret_cast<const float4*>(feat + (size_t)s1 * F);
        #pragma unroll
        for (int v = 0; v < V; v++) {
            float4 t0 = r0[lane + 32 * v];
            float4 t1 = r1[lane + 32 * v];
            acc0[v].x += t0.x; acc0[v].y += t0.y; acc0[v].z += t0.z; acc0[v].w += t0.w;
            acc1[v].x += t1.x; acc1[v].y += t1.y; acc1[v].z += t1.z; acc1[v].w += t1.w;
        }
    }
    if (i < e) {
        int s0 = g_csr[i];
        const float4* r0 = reinterpret_cast<const float4*>(feat + (size_t)s0 * F);
        #pragma unroll
        for (int v = 0; v < V; v++) {
            float4 t0 = r0[lane + 32 * v];
            acc0[v].x += t0.x; acc0[v].y += t0.y; acc0[v].z += t0.z; acc0[v].w += t0.w;
        }
    }
    float inv = (e > s) ? 1.0f / (float)(e - s) : 0.0f;
    float4* orow = reinterpret_cast<float4*>(out + (size_t)node * F);
    #pragma unroll
    for (int v = 0; v < V; v++) {
        float4 o;
        o.x = tf32f((acc0[v].x + acc1[v].x) * inv);
        o.y = tf32f((acc0[v].y + acc1[v].y) * inv);
        o.z = tf32f((acc0[v].z + acc1[v].z) * inv);
        o.w = tf32f((acc0[v].w + acc1[v].w) * inv);
        orow[lane + 32 * v] = o;
    }
}

// ======================= tf32 mma.sync dual GEMM v4 =======================
// Pre-rounded tf32 operands; 3-stage cp.async pipeline, ONE syncthreads per chunk.
// C[M, 256] = act( A1[M,K1] * B1[256,K1]^T + A2[M,K2] * B2[256,K2]^T + bias )

#define GBM 128
#define GBN 256
#define GBK 32
#define GSP 36               // smem row stride in words (32 data + 4 pad)
#define GTHREADS 512
#define NSTAGE 3

#define A_WORDS (GBM * GSP)                    // 4608
#define B_WORDS (GBN * GSP)                    // 9216
#define STAGE_WORDS (A_WORDS + B_WORDS)        // 13824
#define GEMM_SMEM_BYTES (NSTAGE * STAGE_WORDS * 4)   // 165888

__device__ __forceinline__ void mma_tf32(float* d, const uint32_t* a, const uint32_t* b,
                                         const float* c) {
    asm volatile(
        "mma.sync.aligned.m16n8k8.row.col.f32.tf32.tf32.f32 "
        "{%0,%1,%2,%3}, {%4,%5,%6,%7}, {%8,%9}, {%10,%11,%12,%13};"
        : "=f"(d[0]), "=f"(d[1]), "=f"(d[2]), "=f"(d[3])
        : "r"(a[0]), "r"(a[1]), "r"(a[2]), "r"(a[3]),
          "r"(b[0]), "r"(b[1]),
          "f"(c[0]), "f"(c[1]), "f"(c[2]), "f"(c[3]));
}

__device__ __forceinline__ void cp16(uint32_t dst, const float* src, bool ok) {
    int sz = ok ? 16 : 0;
    asm volatile("cp.async.cg.shared.global [%0], [%1], 16, %2;"
                 :: "r"(dst), "l"(src), "r"(sz));
}
#define CP_COMMIT() asm volatile("cp.async.commit_group;" ::: "memory")
#define CP_WAIT(n)  asm volatile("cp.async.wait_group %0;" :: "n"(n) : "memory")

template <bool RELU, bool ROUND_OUT>
__global__ __launch_bounds__(GTHREADS)
void gemm_mma4(const float* __restrict__ A1, const float* __restrict__ B1, int K1,
               const float* __restrict__ A2, const float* __restrict__ B2, int K2,
               const float* __restrict__ bias, float* __restrict__ C, int M) {
    extern __shared__ float gsm[];
    uint32_t sbase;
    asm("{ .reg .u64 t; cvta.to.shared.u64 t, %1; cvt.u32.u64 %0, t; }"
        : "=r"(sbase) : "l"(gsm));

    int tid  = threadIdx.x;
    int wid  = tid >> 5;
    int lane = tid & 31;
    int wm   = wid & 3;           // warp row: 32-row strip
    int wn   = wid >> 2;          // warp col: 64-col strip
    int g    = lane >> 2;         // groupID (0..7)
    int tg   = lane & 3;          // thread-in-group (0..3)

    int m0 = blockIdx.x * GBM;

    const int NC1 = K1 / GBK;
    const int NC  = NC1 + K2 / GBK;   // >= 8

    float acc[2][8][4];
    #pragma unroll
    for (int i = 0; i < 2; i++)
        #pragma unroll
        for (int j = 0; j < 8; j++)
            #pragma unroll
            for (int q = 0; q < 4; q++) acc[i][j][q] = 0.f;

    auto stage = [&](int c, int buf) {
        const float* A; const float* B; int K, k0;
        if (c < NC1) { A = A1; B = B1; K = K1; k0 = c * GBK; }
        else         { A = A2; B = B2; K = K2; k0 = (c - NC1) * GBK; }
        uint32_t abase = sbase + (buf * STAGE_WORDS) * 4;
        uint32_t bbase = abase + A_WORDS * 4;
        #pragma unroll
        for (int l = 0; l < 2; l++) {
            int idx = tid + l * GTHREADS;
            int row = idx >> 3;
            int q   = idx & 7;
            cp16(abase + (row * GSP + q * 4) * 4,
                 A + (size_t)(m0 + row) * K + k0 + q * 4,
                 (m0 + row) < M);
        }
        #pragma unroll
        for (int l = 0; l < 4; l++) {
            int idx = tid + l * GTHREADS;
            int row = idx >> 3;
            int q   = idx & 7;
            cp16(bbase + (row * GSP + q * 4) * 4,
                 B + (size_t)row * K + k0 + q * 4, true);
        }
    };

    stage(0, 0); CP_COMMIT();
    stage(1, 1); CP_COMMIT();

    const uint32_t* usm = reinterpret_cast<const uint32_t*>(gsm);
    int buf = 0;

    for (int c = 0; c < NC; c++) {
        CP_WAIT(1);           // chunk c landed (<=1 group, i.e. c+1, still in flight)
        __syncthreads();      // data visible to all warps; also: everyone done reading buf-1

        const uint32_t* As = usm + buf * STAGE_WORDS;
        const uint32_t* Bs = As + A_WORDS;

        #pragma unroll
        for (int k8 = 0; k8 < 4; k8++) {
            int kk = k8 * 8 + tg;
            uint32_t af[2][4], bf[8][2];
            #pragma unroll
            for (int i = 0; i < 2; i++) {
                int m = wm * 32 + i * 16 + g;
                af[i][0] = As[m * GSP + kk];
                af[i][1] = As[(m + 8) * GSP + kk];
                af[i][2] = As[m * GSP + kk + 4];
                af[i][3] = As[(m + 8) * GSP + kk + 4];
            }
            #pragma unroll
            for (int j = 0; j < 8; j++) {
                int n = wn * 64 + j * 8 + g;
                bf[j][0] = Bs[n * GSP + kk];
                bf[j][1] = Bs[n * GSP + kk + 4];
            }
            #pragma unroll
            for (int i = 0; i < 2; i++)
                #pragma unroll
                for (int j = 0; j < 8; j++)
                    mma_tf32(acc[i][j], af[i], bf[j], acc[i][j]);
        }

        if (c + 2 < NC) {
            int nb = buf + 2; if (nb >= NSTAGE) nb -= NSTAGE;
            stage(c + 2, nb);
            CP_COMMIT();
        } else {
            CP_COMMIT();      // empty group keeps wait_group accounting uniform
        }
        buf = (buf + 1 == NSTAGE) ? 0 : buf + 1;
    }

    // ---- epilogue ----
    #pragma unroll
    for (int i = 0; i < 2; i++) {
        int m = m0 + wm * 32 + i * 16 + g;
        #pragma unroll
        for (int j = 0; j < 8; j++) {
            int n = wn * 64 + j * 8 + 2 * tg;
            float bx = bias[n], by = bias[n + 1];
            if (m < M) {
                float2 v;
                v.x = acc[i][j][0] + bx;
                v.y = acc[i][j][1] + by;
                if (RELU) { v.x = fmaxf(v.x, 0.f); v.y = fmaxf(v.y, 0.f); }
                if (ROUND_OUT) { v.x = tf32f(v.x); v.y = tf32f(v.y); }
                *reinterpret_cast<float2*>(C + (size_t)m * 256 + n) = v;
            }
            if (m + 8 < M) {
                float2 v;
                v.x = acc[i][j][2] + bx;
                v.y = acc[i][j][3] + by;
                if (RELU) { v.x = fmaxf(v.x, 0.f); v.y = fmaxf(v.y, 0.f); }
                if (ROUND_OUT) { v.x = tf32f(v.x); v.y = tf32f(v.y); }
                *reinterpret_cast<float2*>(C + (size_t)(m + 8) * 256 + n) = v;
            }
        }
    }
}

// ---------------- heads: out1 = h@Wh1^T + bh1 (4), out2 = h@Wh2^T + bh2 (3) ----------------
__global__ void heads_kernel(const float* __restrict__ h,
                             const float* __restrict__ Wh1, const float* __restrict__ bh1,
                             const float* __restrict__ Wh2, const float* __restrict__ bh2,
                             float* __restrict__ out1, float* __restrict__ out2) {
    int node = blockIdx.x * (blockDim.x >> 5) + (threadIdx.x >> 5);
    if (node >= N_NODES) return;
    int lane = threadIdx.x & 31;
    const float4* row = reinterpret_cast<const float4*>(h + (size_t)node * HID);
    float4 r0 = row[lane];
    float4 r1 = row[lane + 32];
    float s[7];
    #pragma unroll
    for (int o = 0; o < 7; o++) {
        const float* w = (o < 4) ? (Wh1 + o * HID) : (Wh2 + (o - 4) * HID);
        const float4* wr = reinterpret_cast<const float4*>(w);
        float4 w0 = wr[lane];
        float4 w1 = wr[lane + 32];
        s[o] = r0.x * w0.x + r0.y * w0.y + r0.z * w0.z + r0.w * w0.w
             + r1.x * w1.x + r1.y * w1.y + r1.z * w1.z + r1.w * w1.w;
    }
    #pragma unroll
    for (int o = 0; o < 7; o++)
        #pragma unroll
        for (int d = 16; d > 0; d >>= 1)
            s[o] += __shfl_down_sync(0xffffffffu, s[o], d);
    if (lane == 0) {
        #pragma unroll
        for (int o = 0; o < 4; o++) out1[(size_t)node * 4 + o] = s[o] + bh1[o];
        #pragma unroll
        for (int o = 0; o < 3; o++) out2[(size_t)node * 3 + o] = s[4 + o] + bh2[o];
    }
}

// ---------------- launch ----------------
extern "C" void kernel_launch(void* const* d_in, const int* in_sizes, int n_in,
                              void* d_out, int out_size) {
    const float* x   = (const float*)d_in[0];
    const int*   ei  = (const int*)  d_in[1];
    const float* W1l = (const float*)d_in[2];
    const float* b1l = (const float*)d_in[3];
    const float* W1r = (const float*)d_in[4];
    const float* W2l = (const float*)d_in[5];
    const float* b2l = (const float*)d_in[6];
    const float* W2r = (const float*)d_in[7];
    const float* Wh1 = (const float*)d_in[8];
    const float* bh1 = (const float*)d_in[9];
    const float* Wh2 = (const float*)d_in[10];
    const float* bh2 = (const float*)d_in[11];

    float* out  = (float*)d_out;
    float* out1 = out;                                  // [N,4]
    float* out2 = out + (size_t)N_NODES * 4;            // [N,3]
    float* hout = out + (size_t)N_NODES * 7;            // [N,256]

    const int* src = ei;             // edge_index[0]
    const int* dst = ei + N_EDGES;   // edge_index[1]

    void *p_deg, *p_cur, *p_agg1, *p_h1, *p_agg2, *p_xr, *p_wr;
    cudaGetSymbolAddress(&p_deg,  g_deg);
    cudaGetSymbolAddress(&p_cur,  g_cur);
    cudaGetSymbolAddress(&p_agg1, g_agg1);
    cudaGetSymbolAddress(&p_h1,   g_h1);
    cudaGetSymbolAddress(&p_agg2, g_agg2);
    cudaGetSymbolAddress(&p_xr,   g_xr);
    cudaGetSymbolAddress(&p_wr,   g_wr);
    const float* xr = (const float*)p_xr;
    const float* wr = (const float*)p_wr;

    cudaFuncSetAttribute(gemm_mma4<true, true>,   cudaFuncAttributeMaxDynamicSharedMemorySize, GEMM_SMEM_BYTES);
    cudaFuncSetAttribute(gemm_mma4<false, false>, cudaFuncAttributeMaxDynamicSharedMemorySize, GEMM_SMEM_BYTES);

    cudaMemsetAsync(p_deg, 0, N_NODES * sizeof(int));
    cudaMemsetAsync(p_cur, 0, N_NODES * sizeof(int));

    prep_round<<<(XN4 + WN4 + 255) / 256, 256>>>(x, W1l, W1r, W2l, W2r);

    count_kernel<<<(N_EDGES / 4 + 255) / 256, 256>>>(dst);
    scan1_kernel<<<SCAN_BLOCKS, 256>>>();
    scan2_kernel<<<1, 256>>>();
    scan3_kernel<<<SCAN_BLOCKS, 256>>>();
    fill_kernel<<<(N_EDGES / 4 + 255) / 256, 256>>>(src, dst);

    int gtiles = (N_NODES + GBM - 1) / GBM;   // 391

    // layer 1: h1 = relu(agg1 @ W1l^T + x @ W1r^T + b1l)   [h1 stored tf32-rounded]
    agg_kernel<F_IN><<<(N_NODES + 7) / 8, 256>>>(xr, (float*)p_agg1);
    gemm_mma4<true, true><<<gtiles, GTHREADS, GEMM_SMEM_BYTES>>>(
        (const float*)p_agg1, wr + W1L_OFF, F_IN, xr, wr + W1R_OFF, F_IN,
        b1l, (float*)p_h1, N_NODES);

    // layer 2: hout = agg2 @ W2l^T + h1 @ W2r^T + b2l      [hout exact fp32]
    agg_kernel<HID><<<(N_NODES + 7) / 8, 256>>>((const float*)p_h1, (float*)p_agg2);
    gemm_mma4<false, false><<<gtiles, GTHREADS, GEMM_SMEM_BYTES>>>(
        (const float*)p_agg2, wr + W2L_OFF, HID, (const float*)p_h1, wr + W2R_OFF, HID,
        b2l, hout, N_NODES);

    // heads
    heads_kernel<<<(N_NODES + 7) / 8, 256>>>(hout, Wh1, bh1, Wh2, bh2, out1, out2);
}

// round 7
// speedup vs baseline: 2.4938x; 1.0295x over previous
#include <cuda_runtime.h>
#include <cstdint>

#define N_NODES 50000
#define N_EDGES 800000
#define F_IN    128
#define HID     256

// ---------------- scratch (device globals; no allocation allowed) ----------------
__device__ int   g_deg[N_NODES];
__device__ int   g_off[N_NODES + 1];
__device__ int   g_cur[N_NODES];
__device__ int   g_csr[N_EDGES];
__device__ int   g_bsum[256];
__device__ float g_agg1[(size_t)N_NODES * F_IN];
__device__ float g_h1  [(size_t)N_NODES * HID];
__device__ float g_agg2[(size_t)N_NODES * HID];
__device__ float g_xr  [(size_t)N_NODES * F_IN];   // tf32-rounded x
__device__ float g_wr  [196608];                   // tf32-rounded W1l|W1r|W2l|W2r

#define W1L_OFF 0
#define W1R_OFF 32768
#define W2L_OFF 65536
#define W2R_OFF 131072

__device__ __forceinline__ uint32_t tf32cvt(float x) {
    uint32_t o;
    asm("cvt.rna.tf32.f32 %0, %1;" : "=r"(o) : "f"(x));
    return o;
}
__device__ __forceinline__ float tf32f(float x) { return __uint_as_float(tf32cvt(x)); }

// ---------------- prep: round x and weights to tf32 (float4-vectorized) ----------------
#define XN4 ((N_NODES * F_IN) / 4)      // 1,600,000
#define WN4 (196608 / 4)                // 49,152
__global__ void prep_round(const float* __restrict__ x,
                           const float* __restrict__ w1l, const float* __restrict__ w1r,
                           const float* __restrict__ w2l, const float* __restrict__ w2r) {
    int i = blockIdx.x * blockDim.x + threadIdx.x;
    if (i < XN4) {
        float4 v = reinterpret_cast<const float4*>(x)[i];
        v.x = tf32f(v.x); v.y = tf32f(v.y); v.z = tf32f(v.z); v.w = tf32f(v.w);
        reinterpret_cast<float4*>(g_xr)[i] = v;
        return;
    }
    int j = i - XN4;
    if (j >= WN4) return;
    int e = j * 4;
    const float* s;
    if      (e < W1R_OFF) s = w1l + (e - W1L_OFF);
    else if (e < W2L_OFF) s = w1r + (e - W1R_OFF);
    else if (e < W2R_OFF) s = w2l + (e - W2L_OFF);
    else                  s = w2r + (e - W2R_OFF);
    float4 v = *reinterpret_cast<const float4*>(s);
    v.x = tf32f(v.x); v.y = tf32f(v.y); v.z = tf32f(v.z); v.w = tf32f(v.w);
    reinterpret_cast<float4*>(g_wr)[j] = v;
}

// ---------------- CSR build ----------------
__global__ void count_kernel(const int* __restrict__ dst) {
    int t = blockIdx.x * blockDim.x + threadIdx.x;
    int e0 = t * 4;
    if (e0 >= N_EDGES) return;
    int4 d = *reinterpret_cast<const int4*>(dst + e0);   // N_EDGES % 4 == 0
    atomicAdd(&g_deg[d.x], 1);
    atomicAdd(&g_deg[d.y], 1);
    atomicAdd(&g_deg[d.z], 1);
    atomicAdd(&g_deg[d.w], 1);
}

// 3-kernel parallel exclusive scan of g_deg -> g_off
#define SCAN_BLOCKS 196
__device__ __forceinline__ int warp_incl_scan(int v, int lane) {
    #pragma unroll
    for (int o = 1; o < 32; o <<= 1) {
        int t = __shfl_up_sync(0xffffffffu, v, o);
        if (lane >= o) v += t;
    }
    return v;
}

__global__ void scan1_kernel() {   // grid=196, block=256: local exclusive scan + block sums
    __shared__ int ws[8];
    int tid = threadIdx.x, lane = tid & 31, w = tid >> 5;
    int i = blockIdx.x * 256 + tid;
    int v = (i < N_NODES) ? g_deg[i] : 0;
    int inc = warp_incl_scan(v, lane);
    if (lane == 31) ws[w] = inc;
    __syncthreads();
    if (w == 0) {
        int t = (lane < 8) ? ws[lane] : 0;
        t = warp_incl_scan(t, lane);
        if (lane < 8) ws[lane] = t;
    }
    __syncthreads();
    int base = (w > 0) ? ws[w - 1] : 0;
    if (i < N_NODES) g_off[i] = base + inc - v;
    if (tid == 255) g_bsum[blockIdx.x] = ws[7];
}

__global__ void scan2_kernel() {   // 1 block 256: spine scan
    __shared__ int ws[8];
    int tid = threadIdx.x, lane = tid & 31, w = tid >> 5;
    int v = (tid < SCAN_BLOCKS) ? g_bsum[tid] : 0;
    int inc = warp_incl_scan(v, lane);
    if (lane == 31) ws[w] = inc;
    __syncthreads();
    if (w == 0) {
        int t = (lane < 8) ? ws[lane] : 0;
        t = warp_incl_scan(t, lane);
        if (lane < 8) ws[lane] = t;
    }
    __syncthreads();
    int base = (w > 0) ? ws[w - 1] : 0;
    if (tid < SCAN_BLOCKS) g_bsum[tid] = base + inc - v;   // exclusive
    if (tid == 255) g_off[N_NODES] = ws[7];                // total = N_EDGES
}

__global__ void scan3_kernel() {   // grid=196, block=256: add block offsets
    int i = blockIdx.x * 256 + threadIdx.x;
    if (i < N_NODES) g_off[i] += g_bsum[blockIdx.x];
}

__global__ void fill_kernel(const int* __restrict__ src, const int* __restrict__ dst) {
    int t = blockIdx.x * blockDim.x + threadIdx.x;
    int e0 = t * 4;
    if (e0 >= N_EDGES) return;
    int4 d = *reinterpret_cast<const int4*>(dst + e0);
    int4 s = *reinterpret_cast<const int4*>(src + e0);
    g_csr[g_off[d.x] + atomicAdd(&g_cur[d.x], 1)] = s.x;
    g_csr[g_off[d.y] + atomicAdd(&g_cur[d.y], 1)] = s.y;
    g_csr[g_off[d.z] + atomicAdd(&g_cur[d.z], 1)] = s.z;
    g_csr[g_off[d.w] + atomicAdd(&g_cur[d.w], 1)] = s.w;
}

// ---------------- mean aggregation: one warp per (node, 128-col slice), 4-edge unroll ----------------
template <int SL>   // SL slices of 128 cols; F = SL*128
__global__ void agg_kernel(const float* __restrict__ feat, float* __restrict__ out) {
    constexpr int F = SL * 128;
    int gw = blockIdx.x * (blockDim.x >> 5) + (threadIdx.x >> 5);
    int node  = (SL == 2) ? (gw >> 1) : gw;
    int slice = (SL == 2) ? (gw & 1) : 0;
    if (node >= N_NODES) return;
    int lane = threadIdx.x & 31;
    int col = slice * 128 + lane * 4;

    float4 a0 = make_float4(0.f, 0.f, 0.f, 0.f);
    float4 a1 = a0, a2 = a0, a3 = a0;

    int s = g_off[node], e = g_off[node + 1];
    int i = s;
    for (; i + 3 < e; i += 4) {
        int s0 = g_csr[i], s1 = g_csr[i + 1], s2 = g_csr[i + 2], s3 = g_csr[i + 3];
        float4 t0 = *reinterpret_cast<const float4*>(feat + (size_t)s0 * F + col);
        float4 t1 = *reinterpret_cast<const float4*>(feat + (size_t)s1 * F + col);
        float4 t2 = *reinterpret_cast<const float4*>(feat + (size_t)s2 * F + col);
        float4 t3 = *reinterpret_cast<const float4*>(feat + (size_t)s3 * F + col);
        a0.x += t0.x; a0.y += t0.y; a0.z += t0.z; a0.w += t0.w;
        a1.x += t1.x; a1.y += t1.y; a1.z += t1.z; a1.w += t1.w;
        a2.x += t2.x; a2.y += t2.y; a2.z += t2.z; a2.w += t2.w;
        a3.x += t3.x; a3.y += t3.y; a3.z += t3.z; a3.w += t3.w;
    }
    for (; i < e; i++) {
        int s0 = g_csr[i];
        float4 t0 = *reinterpret_cast<const float4*>(feat + (size_t)s0 * F + col);
        a0.x += t0.x; a0.y += t0.y; a0.z += t0.z; a0.w += t0.w;
    }
    float inv = (e > s) ? 1.0f / (float)(e - s) : 0.0f;
    float4 o;
    o.x = tf32f((a0.x + a1.x + a2.x + a3.x) * inv);
    o.y = tf32f((a0.y + a1.y + a2.y + a3.y) * inv);
    o.z = tf32f((a0.z + a1.z + a2.z + a3.z) * inv);
    o.w = tf32f((a0.w + a1.w + a2.w + a3.w) * inv);
    *reinterpret_cast<float4*>(out + (size_t)node * F + col) = o;
}

// ======================= tf32 mma.sync dual GEMM v5 (+fused heads) =======================
// C[M, 256] = act( A1[M,K1] * B1[256,K1]^T + A2[M,K2] * B2[256,K2]^T + bias )
// HEADS: additionally out1 = C@Wh1^T + bh1 (4), out2 = C@Wh2^T + bh2 (3)

#define GBM 128
#define GBN 256
#define GBK 32
#define GSP 36               // smem row stride in words (32 data + 4 pad)
#define GTHREADS 512
#define NSTAGE 3

#define A_WORDS (GBM * GSP)                    // 4608
#define B_WORDS (GBN * GSP)                    // 9216
#define STAGE_WORDS (A_WORDS + B_WORDS)        // 13824
#define WH_WORDS 1792                          // 7 x 256 head weights
#define PART_WORDS (4 * 128 * 7)               // 3584 cross-warp partials
#define GEMM_SMEM_BYTES  (NSTAGE * STAGE_WORDS * 4)                            // 165888
#define GEMM2_SMEM_BYTES ((NSTAGE * STAGE_WORDS + WH_WORDS + PART_WORDS) * 4)  // 187392

__device__ __forceinline__ void mma_tf32(float* d, const uint32_t* a, const uint32_t* b,
                                         const float* c) {
    asm volatile(
        "mma.sync.aligned.m16n8k8.row.col.f32.tf32.tf32.f32 "
        "{%0,%1,%2,%3}, {%4,%5,%6,%7}, {%8,%9}, {%10,%11,%12,%13};"
        : "=f"(d[0]), "=f"(d[1]), "=f"(d[2]), "=f"(d[3])
        : "r"(a[0]), "r"(a[1]), "r"(a[2]), "r"(a[3]),
          "r"(b[0]), "r"(b[1]),
          "f"(c[0]), "f"(c[1]), "f"(c[2]), "f"(c[3]));
}

__device__ __forceinline__ void cp16(uint32_t dst, const float* src, bool ok) {
    int sz = ok ? 16 : 0;
    asm volatile("cp.async.cg.shared.global [%0], [%1], 16, %2;"
                 :: "r"(dst), "l"(src), "r"(sz));
}
#define CP_COMMIT() asm volatile("cp.async.commit_group;" ::: "memory")
#define CP_WAIT(n)  asm volatile("cp.async.wait_group %0;" :: "n"(n) : "memory")

template <bool RELU, bool ROUND_OUT, bool HEADS>
__global__ __launch_bounds__(GTHREADS)
void gemm_mma5(const float* __restrict__ A1, const float* __restrict__ B1, int K1,
               const float* __restrict__ A2, const float* __restrict__ B2, int K2,
               const float* __restrict__ bias, float* __restrict__ C, int M,
               const float* __restrict__ Wh1, const float* __restrict__ bh1,
               const float* __restrict__ Wh2, const float* __restrict__ bh2,
               float* __restrict__ out1, float* __restrict__ out2) {
    extern __shared__ float gsm[];
    uint32_t sbase;
    asm("{ .reg .u64 t; cvta.to.shared.u64 t, %1; cvt.u32.u64 %0, t; }"
        : "=r"(sbase) : "l"(gsm));

    int tid  = threadIdx.x;
    int wid  = tid >> 5;
    int lane = tid & 31;
    int wm   = wid & 3;           // warp row: 32-row strip
    int wn   = wid >> 2;          // warp col: 64-col strip
    int g    = lane >> 2;         // groupID (0..7)
    int tg   = lane & 3;          // thread-in-group (0..3)

    int m0 = blockIdx.x * GBM;

    float* whs  = gsm + NSTAGE * STAGE_WORDS;
    float* part = whs + WH_WORDS;
    if (HEADS) {
        for (int idx = tid; idx < WH_WORDS; idx += GTHREADS) {
            int o = idx >> 8, cc = idx & 255;
            whs[idx] = (o < 4) ? Wh1[o * 256 + cc] : Wh2[(o - 4) * 256 + cc];
        }
    }

    const int NC1 = K1 / GBK;
    const int NC  = NC1 + K2 / GBK;   // >= 8

    float acc[2][8][4];
    #pragma unroll
    for (int i = 0; i < 2; i++)
        #pragma unroll
        for (int j = 0; j < 8; j++)
            #pragma unroll
            for (int q = 0; q < 4; q++) acc[i][j][q] = 0.f;

    auto stage = [&](int c, int buf) {
        const float* A; const float* B; int K, k0;
        if (c < NC1) { A = A1; B = B1; K = K1; k0 = c * GBK; }
        else         { A = A2; B = B2; K = K2; k0 = (c - NC1) * GBK; }
        uint32_t abase = sbase + (buf * STAGE_WORDS) * 4;
        uint32_t bbase = abase + A_WORDS * 4;
        #pragma unroll
        for (int l = 0; l < 2; l++) {
            int idx = tid + l * GTHREADS;
            int row = idx >> 3;
            int q   = idx & 7;
            cp16(abase + (row * GSP + q * 4) * 4,
                 A + (size_t)(m0 + row) * K + k0 + q * 4,
                 (m0 + row) < M);
        }
        #pragma unroll
        for (int l = 0; l < 4; l++) {
            int idx = tid + l * GTHREADS;
            int row = idx >> 3;
            int q   = idx & 7;
            cp16(bbase + (row * GSP + q * 4) * 4,
                 B + (size_t)row * K + k0 + q * 4, true);
        }
    };

    stage(0, 0); CP_COMMIT();
    stage(1, 1); CP_COMMIT();

    const uint32_t* usm = reinterpret_cast<const uint32_t*>(gsm);
    int buf = 0;

    for (int c = 0; c < NC; c++) {
        CP_WAIT(1);
        __syncthreads();

        const uint32_t* As = usm + buf * STAGE_WORDS;
        const uint32_t* Bs = As + A_WORDS;

        #pragma unroll
        for (int k8 = 0; k8 < 4; k8++) {
            int kk = k8 * 8 + tg;
            uint32_t af[2][4], bf[8][2];
            #pragma unroll
            for (int i = 0; i < 2; i++) {
                int m = wm * 32 + i * 16 + g;
                af[i][0] = As[m * GSP + kk];
                af[i][1] = As[(m + 8) * GSP + kk];
                af[i][2] = As[m * GSP + kk + 4];
                af[i][3] = As[(m + 8) * GSP + kk + 4];
            }
            #pragma unroll
            for (int j = 0; j < 8; j++) {
                int n = wn * 64 + j * 8 + g;
                bf[j][0] = Bs[n * GSP + kk];
                bf[j][1] = Bs[n * GSP + kk + 4];
            }
            #pragma unroll
            for (int i = 0; i < 2; i++)
                #pragma unroll
                for (int j = 0; j < 8; j++)
                    mma_tf32(acc[i][j], af[i], bf[j], acc[i][j]);
        }

        if (c + 2 < NC) {
            int nb = buf + 2; if (nb >= NSTAGE) nb -= NSTAGE;
            stage(c + 2, nb);
            CP_COMMIT();
        } else {
            CP_COMMIT();
        }
        buf = (buf + 1 == NSTAGE) ? 0 : buf + 1;
    }

    // ---- epilogue: store C, accumulate head partials ----
    float hs[4][7];
    if (HEADS) {
        #pragma unroll
        for (int sl = 0; sl < 4; sl++)
            #pragma unroll
            for (int o = 0; o < 7; o++) hs[sl][o] = 0.f;
    }

    #pragma unroll
    for (int i = 0; i < 2; i++) {
        int m = m0 + wm * 32 + i * 16 + g;
        bool ok0 = (m < M), ok1 = (m + 8 < M);
        #pragma unroll
        for (int j = 0; j < 8; j++) {
            int n = wn * 64 + j * 8 + 2 * tg;
            float bx = bias[n], by = bias[n + 1];
            float v0 = acc[i][j][0] + bx, v1 = acc[i][j][1] + by;
            float w0 = acc[i][j][2] + bx, w1 = acc[i][j][3] + by;
            if (RELU) {
                v0 = fmaxf(v0, 0.f); v1 = fmaxf(v1, 0.f);
                w0 = fmaxf(w0, 0.f); w1 = fmaxf(w1, 0.f);
            }
            if (ROUND_OUT) {
                v0 = tf32f(v0); v1 = tf32f(v1);
                w0 = tf32f(w0); w1 = tf32f(w1);
            }
            if (ok0) *reinterpret_cast<float2*>(C + (size_t)m * 256 + n) = make_float2(v0, v1);
            if (ok1) *reinterpret_cast<float2*>(C + (size_t)(m + 8) * 256 + n) = make_float2(w0, w1);
            if (HEADS) {
                #pragma unroll
                for (int o = 0; o < 7; o++) {
                    float wa = whs[o * 256 + n], wb = whs[o * 256 + n + 1];
                    if (ok0) hs[i * 2 + 0][o] += v0 * wa + v1 * wb;
                    if (ok1) hs[i * 2 + 1][o] += w0 * wa + w1 * wb;
                }
            }
        }
    }

    if (HEADS) {
        // reduce over tg lanes (same row, 4 threads)
        #pragma unroll
        for (int sl = 0; sl < 4; sl++)
            #pragma unroll
            for (int o = 0; o < 7; o++) {
                float v = hs[sl][o];
                v += __shfl_xor_sync(0xffffffffu, v, 1);
                v += __shfl_xor_sync(0xffffffffu, v, 2);
                hs[sl][o] = v;
            }
        if (tg == 0) {
            #pragma unroll
            for (int sl = 0; sl < 4; sl++) {
                int i = sl >> 1, h = sl & 1;
                int row = wm * 32 + i * 16 + g + h * 8;
                #pragma unroll
                for (int o = 0; o < 7; o++)
                    part[(wn * 128 + row) * 7 + o] = hs[sl][o];
            }
        }
        __syncthreads();
        if (tid < 128) {
            int m = m0 + tid;
            if (m < M) {
                #pragma unroll
                for (int o = 0; o < 7; o++) {
                    float v = part[(0 * 128 + tid) * 7 + o] + part[(1 * 128 + tid) * 7 + o]
                            + part[(2 * 128 + tid) * 7 + o] + part[(3 * 128 + tid) * 7 + o];
                    if (o < 4) out1[(size_t)m * 4 + o] = v + bh1[o];
                    else       out2[(size_t)m * 3 + (o - 4)] = v + bh2[o - 4];
                }
            }
        }
    }
}

// ---------------- launch ----------------
extern "C" void kernel_launch(void* const* d_in, const int* in_sizes, int n_in,
                              void* d_out, int out_size) {
    const float* x   = (const float*)d_in[0];
    const int*   ei  = (const int*)  d_in[1];
    const float* W1l = (const float*)d_in[2];
    const float* b1l = (const float*)d_in[3];
    const float* W1r = (const float*)d_in[4];
    const float* W2l = (const float*)d_in[5];
    const float* b2l = (const float*)d_in[6];
    const float* W2r = (const float*)d_in[7];
    const float* Wh1 = (const float*)d_in[8];
    const float* bh1 = (const float*)d_in[9];
    const float* Wh2 = (const float*)d_in[10];
    const float* bh2 = (const float*)d_in[11];

    float* out  = (float*)d_out;
    float* out1 = out;                                  // [N,4]
    float* out2 = out + (size_t)N_NODES * 4;            // [N,3]
    float* hout = out + (size_t)N_NODES * 7;            // [N,256]

    const int* src = ei;             // edge_index[0]
    const int* dst = ei + N_EDGES;   // edge_index[1]

    void *p_deg, *p_cur, *p_agg1, *p_h1, *p_agg2, *p_xr, *p_wr;
    cudaGetSymbolAddress(&p_deg,  g_deg);
    cudaGetSymbolAddress(&p_cur,  g_cur);
    cudaGetSymbolAddress(&p_agg1, g_agg1);
    cudaGetSymbolAddress(&p_h1,   g_h1);
    cudaGetSymbolAddress(&p_agg2, g_agg2);
    cudaGetSymbolAddress(&p_xr,   g_xr);
    cudaGetSymbolAddress(&p_wr,   g_wr);
    const float* xr = (const float*)p_xr;
    const float* wr = (const float*)p_wr;

    cudaFuncSetAttribute(gemm_mma5<true, true, false>,
                         cudaFuncAttributeMaxDynamicSharedMemorySize, GEMM_SMEM_BYTES);
    cudaFuncSetAttribute(gemm_mma5<false, false, true>,
                         cudaFuncAttributeMaxDynamicSharedMemorySize, GEMM2_SMEM_BYTES);

    cudaMemsetAsync(p_deg, 0, N_NODES * sizeof(int));
    cudaMemsetAsync(p_cur, 0, N_NODES * sizeof(int));

    prep_round<<<(XN4 + WN4 + 255) / 256, 256>>>(x, W1l, W1r, W2l, W2r);

    count_kernel<<<(N_EDGES / 4 + 255) / 256, 256>>>(dst);
    scan1_kernel<<<SCAN_BLOCKS, 256>>>();
    scan2_kernel<<<1, 256>>>();
    scan3_kernel<<<SCAN_BLOCKS, 256>>>();
    fill_kernel<<<(N_EDGES / 4 + 255) / 256, 256>>>(src, dst);

    int gtiles = (N_NODES + GBM - 1) / GBM;   // 391

    // layer 1: h1 = relu(agg1 @ W1l^T + x @ W1r^T + b1l)   [h1 stored tf32-rounded]
    agg_kernel<1><<<(N_NODES + 7) / 8, 256>>>(xr, (float*)p_agg1);
    gemm_mma5<true, true, false><<<gtiles, GTHREADS, GEMM_SMEM_BYTES>>>(
        (const float*)p_agg1, wr + W1L_OFF, F_IN, xr, wr + W1R_OFF, F_IN,
        b1l, (float*)p_h1, N_NODES,
        nullptr, nullptr, nullptr, nullptr, nullptr, nullptr);

    // layer 2 + heads: hout = agg2 @ W2l^T + h1 @ W2r^T + b2l; out1/out2 fused
    agg_kernel<2><<<(2 * N_NODES + 7) / 8, 256>>>((const float*)p_h1, (float*)p_agg2);
    gemm_mma5<false, false, true><<<gtiles, GTHREADS, GEMM2_SMEM_BYTES>>>(
        (const float*)p_agg2, wr + W2L_OFF, HID, (const float*)p_h1, wr + W2R_OFF, HID,
        b2l, hout, N_NODES,
        Wh1, bh1, Wh2, bh2, out1, out2);
}